// round 3
// baseline (speedup 1.0000x reference)
#include <cuda_runtime.h>
#include <cstdint>

// ===================== problem dims =====================
static constexpr int BATCH    = 16384;
static constexpr int DGPE_IN  = 1536;
static constexpr int DGPE_OUT = 1536;
static constexpr int DGPI_IN  = 3072;
static constexpr int DGPI_OUT = 1536;
static constexpr int U3       = 512;
static constexpr int ACT      = 6;

// ===================== device scratch (no cudaMalloc allowed) =====================
__device__ float g_wt_gpe[DGPE_OUT * DGPE_IN];            // [n][k] masked W^T (tf32-rounded)
__device__ float g_wt_gpi[DGPI_OUT * DGPI_IN];
__device__ float g_wt_w1 [U3 * DGPI_OUT];
__device__ float g_wt_w2 [U3 * U3];
__device__ float g_gpe_out[(size_t)BATCH * DGPE_OUT];
__device__ float g_gpi_out[(size_t)BATCH * DGPI_OUT];
__device__ float g_h1[(size_t)BATCH * U3];
__device__ float g_h2[(size_t)BATCH * U3];

// ===================== helpers =====================
__device__ __forceinline__ uint32_t smem_u32(const void* p) {
    return (uint32_t)__cvta_generic_to_shared(p);
}
__device__ __forceinline__ uint32_t f2tf32(float x) {
    uint32_t r;
    asm("cvt.rna.tf32.f32 %0, %1;" : "=r"(r) : "f"(x));
    return r;
}
#define CP_ASYNC16(dst, src) \
    asm volatile("cp.async.cg.shared.global [%0], [%1], 16;\n" :: "r"(dst), "l"(src))
#define CP_ASYNC_COMMIT() asm volatile("cp.async.commit_group;\n" ::: "memory")
#define CP_ASYNC_WAIT(n)  asm volatile("cp.async.wait_group %0;\n" :: "n"(n) : "memory")

// Swizzled smem tile: rows of 32 floats (128B). 16B chunk c within a row is
// stored at chunk (c ^ (row&7)). Makes both cp.async stores and the MMA
// fragment LDS pattern bank-conflict-free.
__device__ __forceinline__ int swz_idx(int row, int col) {
    int c = (col >> 2) & 7;
    return row * 32 + (((c ^ (row & 7)) << 2) | (col & 3));
}

__device__ __forceinline__ void mma_tf32(float c[4], uint32_t a0, uint32_t a1,
                                         uint32_t a2, uint32_t a3,
                                         uint32_t b0, uint32_t b1) {
    asm volatile(
        "mma.sync.aligned.m16n8k8.row.col.f32.tf32.tf32.f32 "
        "{%0,%1,%2,%3}, {%4,%5,%6,%7}, {%8,%9}, {%0,%1,%2,%3};"
        : "+f"(c[0]), "+f"(c[1]), "+f"(c[2]), "+f"(c[3])
        : "r"(a0), "r"(a1), "r"(a2), "r"(a3), "r"(b0), "r"(b1));
}

// ===================== GEMM config =====================
static constexpr int BM = 128, BN = 128, BK = 32, STAGES = 3, NTHREADS = 256;
static constexpr int A_STAGE_BYTES = BM * BK * 4;                   // 16384
static constexpr int B_STAGE_BYTES = BN * BK * 4;                   // 16384
static constexpr int STAGE_BYTES   = A_STAGE_BYTES + B_STAGE_BYTES; // 32768
static constexpr int SMEM_BIAS     = 0;                             // BN floats
static constexpr int SMEM_TILES    = 1024;
static constexpr int SMEM_TOTAL    = SMEM_TILES + STAGES * STAGE_BYTES; // 99328

// D[m,n] = sum_k A[m,k] * BT[n,k] + bias[n]   (optional ReLU)
// A K-split: k < ksplit -> A0 (lda0) else A1 (lda1, k-ksplit). ksplit % BK == 0.
// Grid: x = N/BN (fast), y = BATCH/BM  -> a wave shares one A row-slab in L2.
__global__ void __launch_bounds__(NTHREADS, 2)
gemm_tf32(const float* __restrict__ A0, const float* __restrict__ A1,
          int ksplit, int lda0, int lda1,
          const float* __restrict__ BT, const float* __restrict__ bias,
          float* __restrict__ D, int N, int K, int do_relu)
{
    extern __shared__ char smem[];
    float* sb_bias = (float*)(smem + SMEM_BIAS);
    const uint32_t stile = smem_u32(smem) + SMEM_TILES;
    const int tid  = threadIdx.x;
    const int wid  = tid >> 5;
    const int lane = tid & 31;
    const int g    = lane >> 2;        // groupID (0..7)
    const int t    = lane & 3;         // thread-in-group (0..3)
    const int m0 = blockIdx.y * BM;
    const int n0 = blockIdx.x * BN;
    const int warp_m = (wid >> 2) * 64;   // 2 warps along M, tile 64
    const int warp_n = (wid & 3) * 32;    // 4 warps along N, tile 32

    if (tid < BN) sb_bias[tid] = bias[n0 + tid];

    const int KB = K / BK;

    auto load_stage = [&](int kb) {
        const int s = kb % STAGES;
        const int k0 = kb * BK;
        const uint32_t a_base = stile + s * STAGE_BYTES;
        const uint32_t b_base = a_base + A_STAGE_BYTES;
        // A: 128 rows x 8 x 16B chunks = 1024 chunks, 4 per thread
        #pragma unroll
        for (int j = 0; j < 4; j++) {
            int idx = tid + j * NTHREADS;
            int row = idx >> 3;
            int c   = idx & 7;
            int kg  = k0 + (c << 2);
            const float* src = (kg < ksplit)
                ? (A0 + (size_t)(m0 + row) * lda0 + kg)
                : (A1 + (size_t)(m0 + row) * lda1 + (kg - ksplit));
            uint32_t dst = a_base + row * 128 + ((c ^ (row & 7)) << 4);
            CP_ASYNC16(dst, src);
        }
        // B: 128 rows x 8 chunks
        #pragma unroll
        for (int j = 0; j < 4; j++) {
            int idx = tid + j * NTHREADS;
            int row = idx >> 3;
            int c   = idx & 7;
            const float* src = BT + (size_t)(n0 + row) * K + k0 + (c << 2);
            uint32_t dst = b_base + row * 128 + ((c ^ (row & 7)) << 4);
            CP_ASYNC16(dst, src);
        }
        CP_ASYNC_COMMIT();
    };

    float acc[4][4][4];
    #pragma unroll
    for (int mt = 0; mt < 4; mt++)
        #pragma unroll
        for (int nt = 0; nt < 4; nt++)
            #pragma unroll
            for (int r = 0; r < 4; r++) acc[mt][nt][r] = 0.f;

    // prologue
    load_stage(0);
    if (KB > 1) load_stage(1);

    for (int kb = 0; kb < KB; kb++) {
        if (kb < KB - 1) { CP_ASYNC_WAIT(1); } else { CP_ASYNC_WAIT(0); }
        __syncthreads();
        if (kb + 2 < KB) load_stage(kb + 2);

        const int s = kb % STAGES;
        const float* As = (const float*)(smem + SMEM_TILES + s * STAGE_BYTES);
        const float* Bs = As + BM * BK;

        #pragma unroll
        for (int ks = 0; ks < 4; ks++) {
            const int kk = ks * 8;
            uint32_t a[4][4], b[4][2];
            #pragma unroll
            for (int mt = 0; mt < 4; mt++) {
                int r0 = warp_m + mt * 16 + g;
                a[mt][0] = f2tf32(As[swz_idx(r0,     kk + t)]);
                a[mt][1] = f2tf32(As[swz_idx(r0 + 8, kk + t)]);
                a[mt][2] = f2tf32(As[swz_idx(r0,     kk + t + 4)]);
                a[mt][3] = f2tf32(As[swz_idx(r0 + 8, kk + t + 4)]);
            }
            #pragma unroll
            for (int nt = 0; nt < 4; nt++) {
                int rn = warp_n + nt * 8 + g;
                b[nt][0] = __float_as_uint(Bs[swz_idx(rn, kk + t)]);
                b[nt][1] = __float_as_uint(Bs[swz_idx(rn, kk + t + 4)]);
            }
            #pragma unroll
            for (int mt = 0; mt < 4; mt++)
                #pragma unroll
                for (int nt = 0; nt < 4; nt++)
                    mma_tf32(acc[mt][nt], a[mt][0], a[mt][1], a[mt][2], a[mt][3],
                             b[nt][0], b[nt][1]);
        }
        __syncthreads();
    }

    // epilogue: bias + optional relu, direct stores
    #pragma unroll
    for (int mt = 0; mt < 4; mt++) {
        const int row = m0 + warp_m + mt * 16 + g;
        #pragma unroll
        for (int nt = 0; nt < 4; nt++) {
            const int cb = warp_n + nt * 8 + t * 2;   // col within block
            const int col = n0 + cb;
            float b0 = sb_bias[cb], b1 = sb_bias[cb + 1];
            float2 v0 = make_float2(acc[mt][nt][0] + b0, acc[mt][nt][1] + b1);
            float2 v1 = make_float2(acc[mt][nt][2] + b0, acc[mt][nt][3] + b1);
            if (do_relu) {
                v0.x = fmaxf(v0.x, 0.f); v0.y = fmaxf(v0.y, 0.f);
                v1.x = fmaxf(v1.x, 0.f); v1.y = fmaxf(v1.y, 0.f);
            }
            *reinterpret_cast<float2*>(D + (size_t)row * N + col)       = v0;
            *reinterpret_cast<float2*>(D + (size_t)(row + 8) * N + col) = v1;
        }
    }
}

// ===================== weight prep: WT[n][k] = tf32_round(w[k][n] * mask[n][k]) ==========
__global__ void transpose_mask(const float* __restrict__ w, const float* __restrict__ mask,
                               float* __restrict__ wt, int K, int N)
{
    __shared__ float tile[32][33];
    const int k0 = blockIdx.x * 32, n0 = blockIdx.y * 32;
    const int tx = threadIdx.x, ty = threadIdx.y;  // 32 x 8
    #pragma unroll
    for (int j = 0; j < 32; j += 8)
        tile[ty + j][tx] = w[(size_t)(k0 + ty + j) * N + n0 + tx];
    __syncthreads();
    #pragma unroll
    for (int j = 0; j < 32; j += 8) {
        const int n = n0 + ty + j, k = k0 + tx;
        float v = tile[tx][ty + j];
        if (mask) v *= mask[(size_t)n * K + k];
        wt[(size_t)n * K + k] = __uint_as_float(f2tf32(v));
    }
}

// ===================== final skinny layer: out = relu(h @ w3 + b3), N=6 =====================
__global__ void final_layer(const float* __restrict__ h, const float* __restrict__ w3,
                            const float* __restrict__ b3, float* __restrict__ out)
{
    __shared__ float sw[U3 * ACT];
    __shared__ float sbb[ACT];
    const int tid = threadIdx.x;
    for (int i = tid; i < U3 * ACT; i += blockDim.x) sw[i] = w3[i];
    if (tid < ACT) sbb[tid] = b3[tid];
    __syncthreads();
    const int wid = tid >> 5, lane = tid & 31;
    const int row = blockIdx.x * (blockDim.x >> 5) + wid;
    const float* hr = h + (size_t)row * U3;
    float acc[ACT] = {0.f, 0.f, 0.f, 0.f, 0.f, 0.f};
    for (int k = lane; k < U3; k += 32) {
        const float x = hr[k];
        #pragma unroll
        for (int n = 0; n < ACT; n++) acc[n] += x * sw[k * ACT + n];
    }
    #pragma unroll
    for (int n = 0; n < ACT; n++)
        #pragma unroll
        for (int off = 16; off; off >>= 1)
            acc[n] += __shfl_xor_sync(0xffffffffu, acc[n], off);
    if (lane < ACT) out[(size_t)row * ACT + lane] = fmaxf(acc[lane] + sbb[lane], 0.f);
}

// ===================== launch =====================
extern "C" void kernel_launch(void* const* d_in, const int* in_sizes, int n_in,
                              void* d_out, int out_size)
{
    const float* x        = (const float*)d_in[0];
    const float* gpe_mask = (const float*)d_in[1];
    const float* gpe_w    = (const float*)d_in[2];
    const float* gpe_b    = (const float*)d_in[3];
    const float* gpi_mask = (const float*)d_in[4];
    const float* gpi_w    = (const float*)d_in[5];
    const float* gpi_b    = (const float*)d_in[6];
    const float* w1       = (const float*)d_in[7];
    const float* b1       = (const float*)d_in[8];
    const float* w2       = (const float*)d_in[9];
    const float* b2       = (const float*)d_in[10];
    const float* w3       = (const float*)d_in[11];
    const float* b3       = (const float*)d_in[12];
    float* out = (float*)d_out;

    float *wt_gpe, *wt_gpi, *wt_w1, *wt_w2, *gpe_o, *gpi_o, *h1, *h2;
    cudaGetSymbolAddress((void**)&wt_gpe, g_wt_gpe);
    cudaGetSymbolAddress((void**)&wt_gpi, g_wt_gpi);
    cudaGetSymbolAddress((void**)&wt_w1,  g_wt_w1);
    cudaGetSymbolAddress((void**)&wt_w2,  g_wt_w2);
    cudaGetSymbolAddress((void**)&gpe_o,  g_gpe_out);
    cudaGetSymbolAddress((void**)&gpi_o,  g_gpi_out);
    cudaGetSymbolAddress((void**)&h1,     g_h1);
    cudaGetSymbolAddress((void**)&h2,     g_h2);

    cudaFuncSetAttribute(gemm_tf32, cudaFuncAttributeMaxDynamicSharedMemorySize, SMEM_TOTAL);

    const dim3 tb(32, 8);
    transpose_mask<<<dim3(DGPE_IN / 32, DGPE_OUT / 32), tb>>>(gpe_w, gpe_mask, wt_gpe, DGPE_IN, DGPE_OUT);
    transpose_mask<<<dim3(DGPI_IN / 32, DGPI_OUT / 32), tb>>>(gpi_w, gpi_mask, wt_gpi, DGPI_IN, DGPI_OUT);
    transpose_mask<<<dim3(DGPI_OUT / 32, U3 / 32), tb>>>(w1, nullptr, wt_w1, DGPI_OUT, U3);
    transpose_mask<<<dim3(U3 / 32, U3 / 32), tb>>>(w2, nullptr, wt_w2, U3, U3);

    // gpe_out = x @ (gpe_w * gpe_mask^T) + gpe_b
    gemm_tf32<<<dim3(DGPE_OUT / BN, BATCH / BM), NTHREADS, SMEM_TOTAL>>>(
        x, x, DGPE_IN, DGPE_IN, DGPE_IN, wt_gpe, gpe_b, gpe_o, DGPE_OUT, DGPE_IN, 0);
    // gpi_out = [x, gpe_out] @ (gpi_w * gpi_mask^T) + gpi_b   (K-split concat)
    gemm_tf32<<<dim3(DGPI_OUT / BN, BATCH / BM), NTHREADS, SMEM_TOTAL>>>(
        x, gpe_o, DGPE_IN, DGPE_IN, DGPE_OUT, wt_gpi, gpi_b, gpi_o, DGPI_OUT, DGPI_IN, 0);
    // h1 = relu(gpi_out @ w1 + b1)
    gemm_tf32<<<dim3(U3 / BN, BATCH / BM), NTHREADS, SMEM_TOTAL>>>(
        gpi_o, gpi_o, DGPI_OUT, DGPI_OUT, DGPI_OUT, wt_w1, b1, h1, U3, DGPI_OUT, 1);
    // h2 = relu(h1 @ w2 + b2)
    gemm_tf32<<<dim3(U3 / BN, BATCH / BM), NTHREADS, SMEM_TOTAL>>>(
        h1, h1, U3, U3, U3, wt_w2, b2, h2, U3, U3, 1);
    // out = relu(h2 @ w3 + b3)
    final_layer<<<BATCH / 8, 256>>>(h2, w3, b3, out);
}

// round 5
// speedup vs baseline: 2.0593x; 2.0593x over previous
#include <cuda_runtime.h>
#include <cuda_fp16.h>
#include <cstdint>

// ===================== problem dims =====================
static constexpr int BATCH    = 16384;
static constexpr int DGPE_IN  = 1536;
static constexpr int DGPE_OUT = 1536;
static constexpr int DGPI_IN  = 3072;
static constexpr int DGPI_OUT = 1536;
static constexpr int U3       = 512;
static constexpr int ACT      = 6;

// ===================== device scratch (no cudaMalloc allowed) =====================
__device__ __half g_xh   [(size_t)BATCH * DGPE_IN];        // x as fp16
__device__ __half g_wt_gpe[DGPE_OUT * DGPE_IN];            // [n][k] masked W^T fp16
__device__ __half g_wt_gpi[DGPI_OUT * DGPI_IN];
__device__ __half g_wt_w1 [U3 * DGPI_OUT];
__device__ __half g_wt_w2 [U3 * U3];
__device__ __half g_gpe_out[(size_t)BATCH * DGPE_OUT];
__device__ __half g_gpi_out[(size_t)BATCH * DGPI_OUT];
__device__ __half g_h1[(size_t)BATCH * U3];
__device__ __half g_h2[(size_t)BATCH * U3];

// ===================== helpers =====================
__device__ __forceinline__ uint32_t smem_u32(const void* p) {
    return (uint32_t)__cvta_generic_to_shared(p);
}
#define CP_ASYNC16(dst, src) \
    asm volatile("cp.async.cg.shared.global [%0], [%1], 16;\n" :: "r"(dst), "l"(src))
#define CP_ASYNC_COMMIT() asm volatile("cp.async.commit_group;\n" ::: "memory")
#define CP_ASYNC_WAIT(n)  asm volatile("cp.async.wait_group %0;\n" :: "n"(n) : "memory")

// SW64 swizzle for 64-byte rows: conflict-free for ldmatrix 8-row access.
__device__ __forceinline__ uint32_t swz64(uint32_t byte_off) {
    return byte_off ^ ((byte_off >> 3) & 0x30);
}

__device__ __forceinline__ void ldmatrix_x4(uint32_t r[4], uint32_t addr) {
    asm volatile("ldmatrix.sync.aligned.m8n8.x4.shared.b16 {%0,%1,%2,%3}, [%4];"
                 : "=r"(r[0]), "=r"(r[1]), "=r"(r[2]), "=r"(r[3]) : "r"(addr));
}

__device__ __forceinline__ void mma_f16(float c[4], const uint32_t a[4],
                                        uint32_t b0, uint32_t b1) {
    asm volatile(
        "mma.sync.aligned.m16n8k16.row.col.f32.f16.f16.f32 "
        "{%0,%1,%2,%3}, {%4,%5,%6,%7}, {%8,%9}, {%0,%1,%2,%3};"
        : "+f"(c[0]), "+f"(c[1]), "+f"(c[2]), "+f"(c[3])
        : "r"(a[0]), "r"(a[1]), "r"(a[2]), "r"(a[3]), "r"(b0), "r"(b1));
}

// ===================== GEMM config =====================
static constexpr int BM = 128, BN = 128, BK = 32, STAGES = 4, NTHREADS = 256;
static constexpr int A_STAGE_BYTES = BM * BK * 2;                   // 8192
static constexpr int B_STAGE_BYTES = BN * BK * 2;                   // 8192
static constexpr int STAGE_BYTES   = A_STAGE_BYTES + B_STAGE_BYTES; // 16384
static constexpr int SMEM_BIAS     = 0;                             // BN floats
static constexpr int SMEM_TILES    = 1024;
static constexpr int SMEM_TOTAL    = SMEM_TILES + STAGES * STAGE_BYTES; // 66560

// D[m,n] = sum_k A[m,k] * BT[n,k] + bias[n]   (optional ReLU), all operands fp16,
// fp32 accumulate, D stored fp16.
// A K-split: k < ksplit -> A0 (lda0) else A1 (lda1, k-ksplit). ksplit % BK == 0.
// Grid: x = N/BN (fast), y = BATCH/BM  -> a wave shares one A row-slab in L2.
__global__ void __launch_bounds__(NTHREADS, 2)
gemm_f16(const __half* __restrict__ A0, const __half* __restrict__ A1,
         int ksplit, int lda0, int lda1,
         const __half* __restrict__ BT, const float* __restrict__ bias,
         __half* __restrict__ D, int N, int K, int do_relu)
{
    extern __shared__ char smem[];
    float* sb_bias = (float*)(smem + SMEM_BIAS);
    const uint32_t stile = smem_u32(smem) + SMEM_TILES;
    const int tid  = threadIdx.x;
    const int wid  = tid >> 5;
    const int lane = tid & 31;
    const int g    = lane >> 2;        // groupID (0..7)
    const int t    = lane & 3;         // thread-in-group (0..3)
    const int m0 = blockIdx.y * BM;
    const int n0 = blockIdx.x * BN;
    const int warp_m = (wid >> 2) * 64;   // 2 warps along M, tile 64
    const int warp_n = (wid & 3) * 32;    // 4 warps along N, tile 32

    if (tid < BN) sb_bias[tid] = bias[n0 + tid];

    const int KB = K / BK;

    auto load_stage = [&](int kb) {
        const int s = kb & (STAGES - 1);
        const int k0 = kb * BK;                       // in halves
        const uint32_t a_base = stile + s * STAGE_BYTES;
        const uint32_t b_base = a_base + A_STAGE_BYTES;
        // A: 128 rows x 4 x 16B chunks = 512 chunks, 2 per thread
        #pragma unroll
        for (int j = 0; j < 2; j++) {
            int idx = tid + j * NTHREADS;
            int row = idx >> 2;
            int c   = idx & 3;                        // 16B chunk = 8 halves
            int kg  = k0 + (c << 3);
            const __half* src = (kg < ksplit)
                ? (A0 + (size_t)(m0 + row) * lda0 + kg)
                : (A1 + (size_t)(m0 + row) * lda1 + (kg - ksplit));
            uint32_t dst = a_base + swz64((uint32_t)(row * 64 + (c << 4)));
            CP_ASYNC16(dst, src);
        }
        // B: 128 rows x 4 chunks
        #pragma unroll
        for (int j = 0; j < 2; j++) {
            int idx = tid + j * NTHREADS;
            int row = idx >> 2;
            int c   = idx & 3;
            const __half* src = BT + (size_t)(n0 + row) * K + k0 + (c << 3);
            uint32_t dst = b_base + swz64((uint32_t)(row * 64 + (c << 4)));
            CP_ASYNC16(dst, src);
        }
        CP_ASYNC_COMMIT();
    };

    float acc[4][4][4];
    #pragma unroll
    for (int mt = 0; mt < 4; mt++)
        #pragma unroll
        for (int nt = 0; nt < 4; nt++)
            #pragma unroll
            for (int r = 0; r < 4; r++) acc[mt][nt][r] = 0.f;

    // ldmatrix per-thread row/k offsets (same pattern for A and B):
    // threads 0-7: rows +0..7, k-lo | 8-15: rows +8..15, k-lo
    // threads 16-23: rows +0..7, k-hi | 24-31: rows +8..15, k-hi
    const int lm_row = (lane & 8) + (lane & 7);
    const int lm_k   = (lane & 16) >> 1;              // 0 or 8 halves

    // prologue: 3 stages in flight
    load_stage(0); load_stage(1); load_stage(2);

    for (int kb = 0; kb < KB; kb++) {
        if (kb < KB - 3) { CP_ASYNC_WAIT(2); } else { CP_ASYNC_WAIT(0); }
        __syncthreads();
        if (kb + 3 < KB) load_stage(kb + 3);

        const int s = kb & (STAGES - 1);
        const uint32_t As = stile + s * STAGE_BYTES;
        const uint32_t Bs = As + A_STAGE_BYTES;

        #pragma unroll
        for (int ks = 0; ks < 2; ks++) {              // BK=32 -> 2 x k16 steps
            const int kk = ks * 16;
            uint32_t am[4][4], bm[2][4];
            #pragma unroll
            for (int mt = 0; mt < 4; mt++) {
                int row = warp_m + mt * 16 + lm_row;
                ldmatrix_x4(am[mt], As + swz64((uint32_t)(row * 64 + (kk + lm_k) * 2)));
            }
            #pragma unroll
            for (int pr = 0; pr < 2; pr++) {
                int row = warp_n + pr * 16 + lm_row;
                ldmatrix_x4(bm[pr], Bs + swz64((uint32_t)(row * 64 + (kk + lm_k) * 2)));
            }
            #pragma unroll
            for (int mt = 0; mt < 4; mt++)
                #pragma unroll
                for (int nt = 0; nt < 4; nt++)
                    mma_f16(acc[mt][nt], am[mt], bm[nt >> 1][nt & 1], bm[nt >> 1][(nt & 1) + 2]);
        }
        __syncthreads();
    }

    // epilogue: bias + optional relu, store fp16
    #pragma unroll
    for (int mt = 0; mt < 4; mt++) {
        const int row = m0 + warp_m + mt * 16 + g;
        #pragma unroll
        for (int nt = 0; nt < 4; nt++) {
            const int cb = warp_n + nt * 8 + t * 2;   // col within block
            const int col = n0 + cb;
            float b0 = sb_bias[cb], b1 = sb_bias[cb + 1];
            float2 v0 = make_float2(acc[mt][nt][0] + b0, acc[mt][nt][1] + b1);
            float2 v1 = make_float2(acc[mt][nt][2] + b0, acc[mt][nt][3] + b1);
            if (do_relu) {
                v0.x = fmaxf(v0.x, 0.f); v0.y = fmaxf(v0.y, 0.f);
                v1.x = fmaxf(v1.x, 0.f); v1.y = fmaxf(v1.y, 0.f);
            }
            *reinterpret_cast<__half2*>(D + (size_t)row * N + col)       = __floats2half2_rn(v0.x, v0.y);
            *reinterpret_cast<__half2*>(D + (size_t)(row + 8) * N + col) = __floats2half2_rn(v1.x, v1.y);
        }
    }
}

// ===================== weight prep: WT[n][k] = f16(w[k][n] * mask[n][k]) ==========
__global__ void transpose_mask(const float* __restrict__ w, const float* __restrict__ mask,
                               __half* __restrict__ wt, int K, int N)
{
    __shared__ float tile[32][33];
    const int k0 = blockIdx.x * 32, n0 = blockIdx.y * 32;
    const int tx = threadIdx.x, ty = threadIdx.y;  // 32 x 8
    #pragma unroll
    for (int j = 0; j < 32; j += 8)
        tile[ty + j][tx] = w[(size_t)(k0 + ty + j) * N + n0 + tx];
    __syncthreads();
    #pragma unroll
    for (int j = 0; j < 32; j += 8) {
        const int n = n0 + ty + j, k = k0 + tx;
        float v = tile[tx][ty + j];
        if (mask) v *= mask[(size_t)n * K + k];
        wt[(size_t)n * K + k] = __float2half_rn(v);
    }
}

// ===================== x fp32 -> fp16 =====================
__global__ void convert_f2h(const float* __restrict__ src, __half* __restrict__ dst, int n)
{
    int i = (blockIdx.x * blockDim.x + threadIdx.x) * 4;
    if (i < n) {
        float4 v = *reinterpret_cast<const float4*>(src + i);
        __half2 lo = __floats2half2_rn(v.x, v.y);
        __half2 hi = __floats2half2_rn(v.z, v.w);
        *reinterpret_cast<__half2*>(dst + i)     = lo;
        *reinterpret_cast<__half2*>(dst + i + 2) = hi;
    }
}

// ===================== final skinny layer: out = relu(h @ w3 + b3), N=6 =====================
__global__ void final_layer(const __half* __restrict__ h, const float* __restrict__ w3,
                            const float* __restrict__ b3, float* __restrict__ out)
{
    __shared__ float sw[U3 * ACT];
    __shared__ float sbb[ACT];
    const int tid = threadIdx.x;
    for (int i = tid; i < U3 * ACT; i += blockDim.x) sw[i] = w3[i];
    if (tid < ACT) sbb[tid] = b3[tid];
    __syncthreads();
    const int wid = tid >> 5, lane = tid & 31;
    const int row = blockIdx.x * (blockDim.x >> 5) + wid;
    const __half* hr = h + (size_t)row * U3;
    float acc[ACT] = {0.f, 0.f, 0.f, 0.f, 0.f, 0.f};
    for (int k0 = lane * 2; k0 < U3; k0 += 64) {
        __half2 hv = *reinterpret_cast<const __half2*>(hr + k0);
        float x0 = __half2float(hv.x), x1 = __half2float(hv.y);
        #pragma unroll
        for (int n = 0; n < ACT; n++)
            acc[n] += x0 * sw[k0 * ACT + n] + x1 * sw[(k0 + 1) * ACT + n];
    }
    #pragma unroll
    for (int n = 0; n < ACT; n++)
        #pragma unroll
        for (int off = 16; off; off >>= 1)
            acc[n] += __shfl_xor_sync(0xffffffffu, acc[n], off);
    if (lane < ACT) out[(size_t)row * ACT + lane] = fmaxf(acc[lane] + sbb[lane], 0.f);
}

// ===================== launch =====================
extern "C" void kernel_launch(void* const* d_in, const int* in_sizes, int n_in,
                              void* d_out, int out_size)
{
    const float* x        = (const float*)d_in[0];
    const float* gpe_mask = (const float*)d_in[1];
    const float* gpe_w    = (const float*)d_in[2];
    const float* gpe_b    = (const float*)d_in[3];
    const float* gpi_mask = (const float*)d_in[4];
    const float* gpi_w    = (const float*)d_in[5];
    const float* gpi_b    = (const float*)d_in[6];
    const float* w1       = (const float*)d_in[7];
    const float* b1       = (const float*)d_in[8];
    const float* w2       = (const float*)d_in[9];
    const float* b2       = (const float*)d_in[10];
    const float* w3       = (const float*)d_in[11];
    const float* b3       = (const float*)d_in[12];
    float* out = (float*)d_out;

    __half *xh, *wt_gpe, *wt_gpi, *wt_w1, *wt_w2, *gpe_o, *gpi_o, *h1, *h2;
    cudaGetSymbolAddress((void**)&xh,     g_xh);
    cudaGetSymbolAddress((void**)&wt_gpe, g_wt_gpe);
    cudaGetSymbolAddress((void**)&wt_gpi, g_wt_gpi);
    cudaGetSymbolAddress((void**)&wt_w1,  g_wt_w1);
    cudaGetSymbolAddress((void**)&wt_w2,  g_wt_w2);
    cudaGetSymbolAddress((void**)&gpe_o,  g_gpe_out);
    cudaGetSymbolAddress((void**)&gpi_o,  g_gpi_out);
    cudaGetSymbolAddress((void**)&h1,     g_h1);
    cudaGetSymbolAddress((void**)&h2,     g_h2);

    cudaFuncSetAttribute(gemm_f16, cudaFuncAttributeMaxDynamicSharedMemorySize, SMEM_TOTAL);

    const dim3 tb(32, 8);
    const int nx = BATCH * DGPE_IN;
    convert_f2h<<<(nx / 4 + 255) / 256, 256>>>(x, xh, nx);
    transpose_mask<<<dim3(DGPE_IN / 32, DGPE_OUT / 32), tb>>>(gpe_w, gpe_mask, wt_gpe, DGPE_IN, DGPE_OUT);
    transpose_mask<<<dim3(DGPI_IN / 32, DGPI_OUT / 32), tb>>>(gpi_w, gpi_mask, wt_gpi, DGPI_IN, DGPI_OUT);
    transpose_mask<<<dim3(DGPI_OUT / 32, U3 / 32), tb>>>(w1, nullptr, wt_w1, DGPI_OUT, U3);
    transpose_mask<<<dim3(U3 / 32, U3 / 32), tb>>>(w2, nullptr, wt_w2, U3, U3);

    // gpe_out = x @ (gpe_w * gpe_mask^T) + gpe_b
    gemm_f16<<<dim3(DGPE_OUT / BN, BATCH / BM), NTHREADS, SMEM_TOTAL>>>(
        xh, xh, DGPE_IN, DGPE_IN, DGPE_IN, wt_gpe, gpe_b, gpe_o, DGPE_OUT, DGPE_IN, 0);
    // gpi_out = [x, gpe_out] @ (gpi_w * gpi_mask^T) + gpi_b   (K-split concat)
    gemm_f16<<<dim3(DGPI_OUT / BN, BATCH / BM), NTHREADS, SMEM_TOTAL>>>(
        xh, gpe_o, DGPE_IN, DGPE_IN, DGPE_OUT, wt_gpi, gpi_b, gpi_o, DGPI_OUT, DGPI_IN, 0);
    // h1 = relu(gpi_out @ w1 + b1)
    gemm_f16<<<dim3(U3 / BN, BATCH / BM), NTHREADS, SMEM_TOTAL>>>(
        gpi_o, gpi_o, DGPI_OUT, DGPI_OUT, DGPI_OUT, wt_w1, b1, h1, U3, DGPI_OUT, 1);
    // h2 = relu(h1 @ w2 + b2)
    gemm_f16<<<dim3(U3 / BN, BATCH / BM), NTHREADS, SMEM_TOTAL>>>(
        h1, h1, U3, U3, U3, wt_w2, b2, h2, U3, U3, 1);
    // out = relu(h2 @ w3 + b3)
    final_layer<<<BATCH / 8, 256>>>(h2, w3, b3, out);
}

// round 6
// speedup vs baseline: 3.9144x; 1.9008x over previous
#include <cuda_runtime.h>
#include <cuda_fp16.h>
#include <cstdint>

// ===================== problem dims =====================
static constexpr int BATCH    = 16384;
static constexpr int DGPE_IN  = 1536;
static constexpr int DGPE_OUT = 1536;
static constexpr int DGPI_IN  = 3072;
static constexpr int DGPI_OUT = 1536;
static constexpr int U3       = 512;
static constexpr int ACT      = 6;

// ===================== device scratch (no cudaMalloc allowed) =====================
__device__ __half g_xh     [(size_t)BATCH * DGPE_IN];      // x as fp16
__device__ __half g_wt_gpi [DGPI_OUT * DGPI_IN];           // [n][k] masked W^T fp16 (k in 0..3072)
__device__ __half g_wm_gpe [DGPE_IN * DGPE_OUT];           // [i][j] masked gpe W (NOT transposed)
__device__ __half g_weff   [DGPI_OUT * DGPE_IN];           // [n][i] fused effective weight
__device__ float  g_bias_eff[DGPI_OUT];
__device__ __half g_wt_w1  [U3 * DGPI_OUT];
__device__ __half g_wt_w2  [U3 * U3];
__device__ __half g_gpi_out[(size_t)BATCH * DGPI_OUT];
__device__ __half g_h1[(size_t)BATCH * U3];
__device__ __half g_h2[(size_t)BATCH * U3];

// ===================== helpers =====================
__device__ __forceinline__ uint32_t smem_u32(const void* p) {
    return (uint32_t)__cvta_generic_to_shared(p);
}
#define CP_ASYNC16(dst, src) \
    asm volatile("cp.async.cg.shared.global [%0], [%1], 16;\n" :: "r"(dst), "l"(src))
#define CP_ASYNC_COMMIT() asm volatile("cp.async.commit_group;\n" ::: "memory")
#define CP_ASYNC_WAIT(n)  asm volatile("cp.async.wait_group %0;\n" :: "n"(n) : "memory")

// SW64 swizzle for 64-byte rows: conflict-free for ldmatrix 8-row access.
__device__ __forceinline__ uint32_t swz64(uint32_t byte_off) {
    return byte_off ^ ((byte_off >> 3) & 0x30);
}

__device__ __forceinline__ void ldmatrix_x4(uint32_t r[4], uint32_t addr) {
    asm volatile("ldmatrix.sync.aligned.m8n8.x4.shared.b16 {%0,%1,%2,%3}, [%4];"
                 : "=r"(r[0]), "=r"(r[1]), "=r"(r[2]), "=r"(r[3]) : "r"(addr));
}

__device__ __forceinline__ void mma_f16(float c[4], const uint32_t a[4],
                                        uint32_t b0, uint32_t b1) {
    asm volatile(
        "mma.sync.aligned.m16n8k16.row.col.f32.f16.f16.f32 "
        "{%0,%1,%2,%3}, {%4,%5,%6,%7}, {%8,%9}, {%0,%1,%2,%3};"
        : "+f"(c[0]), "+f"(c[1]), "+f"(c[2]), "+f"(c[3])
        : "r"(a[0]), "r"(a[1]), "r"(a[2]), "r"(a[3]), "r"(b0), "r"(b1));
}

// ===================== GEMM config =====================
static constexpr int BM = 128, BN = 128, BK = 32, STAGES = 4, NTHREADS = 256;
static constexpr int A_STAGE_BYTES = BM * BK * 2;                   // 8192
static constexpr int B_STAGE_BYTES = BN * BK * 2;                   // 8192
static constexpr int STAGE_BYTES   = A_STAGE_BYTES + B_STAGE_BYTES; // 16384
static constexpr int SMEM_BIAS     = 0;                             // BN floats
static constexpr int SMEM_TILES    = 1024;
static constexpr int SMEM_TOTAL    = SMEM_TILES + STAGES * STAGE_BYTES; // 66560

// D[m,n] = sum_k A[m,k] * BT[n,k] (+ bias[n]) (+ Cadd[m,n]) (optional ReLU)
// all operands fp16, fp32 accumulate, D stored fp16.
// A K-split: k < ksplit -> A0 (lda0) else A1 (lda1, k-ksplit). ksplit % BK == 0.
__global__ void __launch_bounds__(NTHREADS, 2)
gemm_f16(const __half* __restrict__ A0, const __half* __restrict__ A1,
         int ksplit, int lda0, int lda1,
         const __half* __restrict__ BT, const float* __restrict__ bias,
         const __half* __restrict__ Cadd, int ldc,
         __half* __restrict__ D, int N, int K, int do_relu)
{
    extern __shared__ char smem[];
    float* sb_bias = (float*)(smem + SMEM_BIAS);
    const uint32_t stile = smem_u32(smem) + SMEM_TILES;
    const int tid  = threadIdx.x;
    const int wid  = tid >> 5;
    const int lane = tid & 31;
    const int g    = lane >> 2;        // groupID (0..7)
    const int t    = lane & 3;         // thread-in-group (0..3)
    const int m0 = blockIdx.y * BM;
    const int n0 = blockIdx.x * BN;
    const int warp_m = (wid >> 2) * 64;   // 2 warps along M, tile 64
    const int warp_n = (wid & 3) * 32;    // 4 warps along N, tile 32

    if (tid < BN) sb_bias[tid] = bias ? bias[n0 + tid] : 0.f;

    const int KB = K / BK;

    auto load_stage = [&](int kb) {
        const int s = kb & (STAGES - 1);
        const int k0 = kb * BK;                       // in halves
        const uint32_t a_base = stile + s * STAGE_BYTES;
        const uint32_t b_base = a_base + A_STAGE_BYTES;
        #pragma unroll
        for (int j = 0; j < 2; j++) {
            int idx = tid + j * NTHREADS;
            int row = idx >> 2;
            int c   = idx & 3;                        // 16B chunk = 8 halves
            int kg  = k0 + (c << 3);
            const __half* src = (kg < ksplit)
                ? (A0 + (size_t)(m0 + row) * lda0 + kg)
                : (A1 + (size_t)(m0 + row) * lda1 + (kg - ksplit));
            uint32_t dst = a_base + swz64((uint32_t)(row * 64 + (c << 4)));
            CP_ASYNC16(dst, src);
        }
        #pragma unroll
        for (int j = 0; j < 2; j++) {
            int idx = tid + j * NTHREADS;
            int row = idx >> 2;
            int c   = idx & 3;
            const __half* src = BT + (size_t)(n0 + row) * K + k0 + (c << 3);
            uint32_t dst = b_base + swz64((uint32_t)(row * 64 + (c << 4)));
            CP_ASYNC16(dst, src);
        }
        CP_ASYNC_COMMIT();
    };

    float acc[4][4][4];
    #pragma unroll
    for (int mt = 0; mt < 4; mt++)
        #pragma unroll
        for (int nt = 0; nt < 4; nt++)
            #pragma unroll
            for (int r = 0; r < 4; r++) acc[mt][nt][r] = 0.f;

    const int lm_row = (lane & 8) + (lane & 7);
    const int lm_k   = (lane & 16) >> 1;              // 0 or 8 halves

    load_stage(0); load_stage(1); load_stage(2);

    for (int kb = 0; kb < KB; kb++) {
        if (kb < KB - 3) { CP_ASYNC_WAIT(2); } else { CP_ASYNC_WAIT(0); }
        __syncthreads();   // also orders: all warps done computing stage (kb-1) before overwrite below
        if (kb + 3 < KB) load_stage(kb + 3);

        const int s = kb & (STAGES - 1);
        const uint32_t As = stile + s * STAGE_BYTES;
        const uint32_t Bs = As + A_STAGE_BYTES;

        #pragma unroll
        for (int ks = 0; ks < 2; ks++) {              // BK=32 -> 2 x k16 steps
            const int kk = ks * 16;
            uint32_t am[4][4], bm[2][4];
            #pragma unroll
            for (int mt = 0; mt < 4; mt++) {
                int row = warp_m + mt * 16 + lm_row;
                ldmatrix_x4(am[mt], As + swz64((uint32_t)(row * 64 + (kk + lm_k) * 2)));
            }
            #pragma unroll
            for (int pr = 0; pr < 2; pr++) {
                int row = warp_n + pr * 16 + lm_row;
                ldmatrix_x4(bm[pr], Bs + swz64((uint32_t)(row * 64 + (kk + lm_k) * 2)));
            }
            #pragma unroll
            for (int mt = 0; mt < 4; mt++)
                #pragma unroll
                for (int nt = 0; nt < 4; nt++)
                    mma_f16(acc[mt][nt], am[mt], bm[nt >> 1][nt & 1], bm[nt >> 1][(nt & 1) + 2]);
        }
    }

    // epilogue: bias + optional Cadd + optional relu, store fp16
    #pragma unroll
    for (int mt = 0; mt < 4; mt++) {
        const int row = m0 + warp_m + mt * 16 + g;
        #pragma unroll
        for (int nt = 0; nt < 4; nt++) {
            const int cb = warp_n + nt * 8 + t * 2;   // col within block
            const int col = n0 + cb;
            float b0 = sb_bias[cb], b1 = sb_bias[cb + 1];
            float2 v0 = make_float2(acc[mt][nt][0] + b0, acc[mt][nt][1] + b1);
            float2 v1 = make_float2(acc[mt][nt][2] + b0, acc[mt][nt][3] + b1);
            if (Cadd) {
                __half2 c0 = *reinterpret_cast<const __half2*>(Cadd + (size_t)row * ldc + col);
                __half2 c1 = *reinterpret_cast<const __half2*>(Cadd + (size_t)(row + 8) * ldc + col);
                v0.x += __half2float(c0.x); v0.y += __half2float(c0.y);
                v1.x += __half2float(c1.x); v1.y += __half2float(c1.y);
            }
            if (do_relu) {
                v0.x = fmaxf(v0.x, 0.f); v0.y = fmaxf(v0.y, 0.f);
                v1.x = fmaxf(v1.x, 0.f); v1.y = fmaxf(v1.y, 0.f);
            }
            *reinterpret_cast<__half2*>(D + (size_t)row * N + col)       = __floats2half2_rn(v0.x, v0.y);
            *reinterpret_cast<__half2*>(D + (size_t)(row + 8) * N + col) = __floats2half2_rn(v1.x, v1.y);
        }
    }
}

// ===================== weight prep: WT[n][k] = f16(w[k][n] * mask[n][k]) ==========
__global__ void transpose_mask(const float* __restrict__ w, const float* __restrict__ mask,
                               __half* __restrict__ wt, int K, int N)
{
    __shared__ float tile[32][33];
    const int k0 = blockIdx.x * 32, n0 = blockIdx.y * 32;
    const int tx = threadIdx.x, ty = threadIdx.y;  // 32 x 8
    #pragma unroll
    for (int j = 0; j < 32; j += 8)
        tile[ty + j][tx] = w[(size_t)(k0 + ty + j) * N + n0 + tx];
    __syncthreads();
    #pragma unroll
    for (int j = 0; j < 32; j += 8) {
        const int n = n0 + ty + j, k = k0 + tx;
        float v = tile[tx][ty + j];
        if (mask) v *= mask[(size_t)n * K + k];
        wt[(size_t)n * K + k] = __float2half_rn(v);
    }
}

// ===================== non-transposed masked gpe weight: out[i][j] = w[i][j]*mask[j][i] ======
__global__ void mask_apply_nt(const float* __restrict__ w, const float* __restrict__ mask,
                              __half* __restrict__ out, int I, int J)
{
    __shared__ float mt[32][33];
    const int i0 = blockIdx.y * 32, j0 = blockIdx.x * 32;
    const int tx = threadIdx.x, ty = threadIdx.y;  // 32 x 8
    #pragma unroll
    for (int jj = 0; jj < 32; jj += 8)
        mt[ty + jj][tx] = mask[(size_t)(j0 + ty + jj) * I + i0 + tx];
    __syncthreads();
    #pragma unroll
    for (int jj = 0; jj < 32; jj += 8) {
        const int i = i0 + ty + jj, j = j0 + tx;
        out[(size_t)i * J + j] = __float2half_rn(w[(size_t)i * J + j] * mt[tx][ty + jj]);
    }
}

// ===================== bias_eff[n] = gpi_b[n] + sum_j gpe_b[j] * wt_gpi[n][1536+j] ==========
__global__ void bias_eff_kernel(const __half* __restrict__ wt_gpi, const float* __restrict__ gpe_b,
                                const float* __restrict__ gpi_b, float* __restrict__ be)
{
    const int n = blockIdx.x * 8 + (threadIdx.x >> 5);
    const int lane = threadIdx.x & 31;
    const __half* row = wt_gpi + (size_t)n * DGPI_IN + DGPE_IN;
    float s = 0.f;
    for (int j = lane; j < DGPE_OUT; j += 32)
        s += __half2float(row[j]) * gpe_b[j];
    #pragma unroll
    for (int off = 16; off; off >>= 1) s += __shfl_xor_sync(0xffffffffu, s, off);
    if (lane == 0) be[n] = gpi_b[n] + s;
}

// ===================== x fp32 -> fp16 =====================
__global__ void convert_f2h(const float* __restrict__ src, __half* __restrict__ dst, int n)
{
    int i = (blockIdx.x * blockDim.x + threadIdx.x) * 4;
    if (i < n) {
        float4 v = *reinterpret_cast<const float4*>(src + i);
        *reinterpret_cast<__half2*>(dst + i)     = __floats2half2_rn(v.x, v.y);
        *reinterpret_cast<__half2*>(dst + i + 2) = __floats2half2_rn(v.z, v.w);
    }
}

// ===================== final skinny layer: out = relu(h @ w3 + b3), N=6 =====================
__global__ void final_layer(const __half* __restrict__ h, const float* __restrict__ w3,
                            const float* __restrict__ b3, float* __restrict__ out)
{
    __shared__ float sw[U3 * ACT];
    __shared__ float sbb[ACT];
    const int tid = threadIdx.x;
    for (int i = tid; i < U3 * ACT; i += blockDim.x) sw[i] = w3[i];
    if (tid < ACT) sbb[tid] = b3[tid];
    __syncthreads();
    const int wid = tid >> 5, lane = tid & 31;
    const int row = blockIdx.x * (blockDim.x >> 5) + wid;
    const __half* hr = h + (size_t)row * U3;
    float acc[ACT] = {0.f, 0.f, 0.f, 0.f, 0.f, 0.f};
    for (int k0 = lane * 2; k0 < U3; k0 += 64) {
        __half2 hv = *reinterpret_cast<const __half2*>(hr + k0);
        float x0 = __half2float(hv.x), x1 = __half2float(hv.y);
        #pragma unroll
        for (int n = 0; n < ACT; n++)
            acc[n] += x0 * sw[k0 * ACT + n] + x1 * sw[(k0 + 1) * ACT + n];
    }
    #pragma unroll
    for (int n = 0; n < ACT; n++)
        #pragma unroll
        for (int off = 16; off; off >>= 1)
            acc[n] += __shfl_xor_sync(0xffffffffu, acc[n], off);
    if (lane < ACT) out[(size_t)row * ACT + lane] = fmaxf(acc[lane] + sbb[lane], 0.f);
}

// ===================== launch =====================
extern "C" void kernel_launch(void* const* d_in, const int* in_sizes, int n_in,
                              void* d_out, int out_size)
{
    const float* x        = (const float*)d_in[0];
    const float* gpe_mask = (const float*)d_in[1];
    const float* gpe_w    = (const float*)d_in[2];
    const float* gpe_b    = (const float*)d_in[3];
    const float* gpi_mask = (const float*)d_in[4];
    const float* gpi_w    = (const float*)d_in[5];
    const float* gpi_b    = (const float*)d_in[6];
    const float* w1       = (const float*)d_in[7];
    const float* b1       = (const float*)d_in[8];
    const float* w2       = (const float*)d_in[9];
    const float* b2       = (const float*)d_in[10];
    const float* w3       = (const float*)d_in[11];
    const float* b3       = (const float*)d_in[12];
    float* out = (float*)d_out;

    __half *xh, *wt_gpi, *wm_gpe, *weff, *wt_w1, *wt_w2, *gpi_o, *h1, *h2;
    float* bias_eff;
    cudaGetSymbolAddress((void**)&xh,       g_xh);
    cudaGetSymbolAddress((void**)&wt_gpi,   g_wt_gpi);
    cudaGetSymbolAddress((void**)&wm_gpe,   g_wm_gpe);
    cudaGetSymbolAddress((void**)&weff,     g_weff);
    cudaGetSymbolAddress((void**)&bias_eff, g_bias_eff);
    cudaGetSymbolAddress((void**)&wt_w1,    g_wt_w1);
    cudaGetSymbolAddress((void**)&wt_w2,    g_wt_w2);
    cudaGetSymbolAddress((void**)&gpi_o,    g_gpi_out);
    cudaGetSymbolAddress((void**)&h1,       g_h1);
    cudaGetSymbolAddress((void**)&h2,       g_h2);

    cudaFuncSetAttribute(gemm_f16, cudaFuncAttributeMaxDynamicSharedMemorySize, SMEM_TOTAL);

    const dim3 tb(32, 8);
    const int nx = BATCH * DGPE_IN;
    convert_f2h<<<(nx / 4 + 255) / 256, 256>>>(x, xh, nx);
    transpose_mask<<<dim3(DGPI_IN / 32, DGPI_OUT / 32), tb>>>(gpi_w, gpi_mask, wt_gpi, DGPI_IN, DGPI_OUT);
    transpose_mask<<<dim3(DGPI_OUT / 32, U3 / 32), tb>>>(w1, nullptr, wt_w1, DGPI_OUT, U3);
    transpose_mask<<<dim3(U3 / 32, U3 / 32), tb>>>(w2, nullptr, wt_w2, U3, U3);
    mask_apply_nt<<<dim3(DGPE_OUT / 32, DGPE_IN / 32), tb>>>(gpe_w, gpe_mask, wm_gpe, DGPE_IN, DGPE_OUT);
    bias_eff_kernel<<<DGPI_OUT / 8, 256>>>(wt_gpi, gpe_b, gpi_b, bias_eff);

    // W_eff[n][i] = wt_gpi[n][i] + sum_j wt_gpi[n][1536+j] * wm_gpe[i][j]   (7.2 GF)
    gemm_f16<<<dim3(DGPE_IN / BN, DGPI_OUT / BM), NTHREADS, SMEM_TOTAL>>>(
        wt_gpi + DGPE_IN, wt_gpi + DGPE_IN, DGPE_OUT, DGPI_IN, DGPI_IN,
        wm_gpe, nullptr, wt_gpi, DGPI_IN, weff, DGPE_IN, DGPE_OUT, 0);
    // gpi_out = x @ W_eff^T + bias_eff    (77 GF; replaces GEMM1+GEMM2)
    gemm_f16<<<dim3(DGPI_OUT / BN, BATCH / BM), NTHREADS, SMEM_TOTAL>>>(
        xh, xh, DGPE_IN, DGPE_IN, DGPE_IN, weff, bias_eff, nullptr, 0,
        gpi_o, DGPI_OUT, DGPE_IN, 0);
    // h1 = relu(gpi_out @ w1 + b1)
    gemm_f16<<<dim3(U3 / BN, BATCH / BM), NTHREADS, SMEM_TOTAL>>>(
        gpi_o, gpi_o, DGPI_OUT, DGPI_OUT, DGPI_OUT, wt_w1, b1, nullptr, 0,
        h1, U3, DGPI_OUT, 1);
    // h2 = relu(h1 @ w2 + b2)
    gemm_f16<<<dim3(U3 / BN, BATCH / BM), NTHREADS, SMEM_TOTAL>>>(
        h1, h1, U3, U3, U3, wt_w2, b2, nullptr, 0, h2, U3, U3, 1);
    // out = relu(h2 @ w3 + b3)
    final_layer<<<BATCH / 8, 256>>>(h2, w3, b3, out);
}

// round 7
// speedup vs baseline: 4.7270x; 1.2076x over previous
#include <cuda_runtime.h>
#include <cuda_fp16.h>
#include <cstdint>

// ===================== problem dims =====================
static constexpr int BATCH    = 16384;
static constexpr int DGPE_IN  = 1536;
static constexpr int DGPE_OUT = 1536;
static constexpr int DGPI_IN  = 3072;
static constexpr int DGPI_OUT = 1536;
static constexpr int U3       = 512;
static constexpr int ACT      = 6;

// ===================== device scratch (no cudaMalloc allowed) =====================
__device__ __half g_xh     [(size_t)BATCH * DGPE_IN];      // x as fp16
__device__ __half g_wt_gpi [DGPI_OUT * DGPI_IN];           // [j][k'] masked gpi W^T fp16 (k' 0..3072)
__device__ __half g_wm_gpe [DGPE_IN * DGPE_OUT];           // [i][k] masked gpe W (non-transposed)
__device__ float  g_wx32   [DGPE_IN * DGPI_OUT];           // [i][j] masked Wx (fp32, exact)
__device__ float  g_weff32 [DGPE_IN * DGPI_OUT];           // [i][j] W_eff^T fp32
__device__ __half g_weffs  [DGPE_IN * 2 * DGPI_OUT];       // [i][ lo(1536) | hi(1536) ]
__device__ __half g_w1s    [U3 * 2 * DGPI_OUT];            // [n][ hi(1536) | lo(1536) ]
__device__ float  g_wfull32[U3 * DGPE_IN];                 // [n][i] fp32 partial
__device__ __half g_wfull_h[U3 * DGPE_IN];                 // [n][i] fp16 final
__device__ float  g_bias_eff[DGPI_OUT];
__device__ float  g_bias_full[U3];
__device__ __half g_wt_w2  [U3 * U3];
__device__ __half g_h1[(size_t)BATCH * U3];
__device__ __half g_h2[(size_t)BATCH * U3];

// ===================== helpers =====================
__device__ __forceinline__ uint32_t smem_u32(const void* p) {
    return (uint32_t)__cvta_generic_to_shared(p);
}
#define CP_ASYNC16(dst, src) \
    asm volatile("cp.async.cg.shared.global [%0], [%1], 16;\n" :: "r"(dst), "l"(src))
#define CP_ASYNC_COMMIT() asm volatile("cp.async.commit_group;\n" ::: "memory")
#define CP_ASYNC_WAIT(n)  asm volatile("cp.async.wait_group %0;\n" :: "n"(n) : "memory")

__device__ __forceinline__ uint32_t swz64(uint32_t byte_off) {
    return byte_off ^ ((byte_off >> 3) & 0x30);
}

__device__ __forceinline__ void ldmatrix_x4(uint32_t r[4], uint32_t addr) {
    asm volatile("ldmatrix.sync.aligned.m8n8.x4.shared.b16 {%0,%1,%2,%3}, [%4];"
                 : "=r"(r[0]), "=r"(r[1]), "=r"(r[2]), "=r"(r[3]) : "r"(addr));
}

__device__ __forceinline__ void mma_f16(float c[4], const uint32_t a[4],
                                        uint32_t b0, uint32_t b1) {
    asm volatile(
        "mma.sync.aligned.m16n8k16.row.col.f32.f16.f16.f32 "
        "{%0,%1,%2,%3}, {%4,%5,%6,%7}, {%8,%9}, {%0,%1,%2,%3};"
        : "+f"(c[0]), "+f"(c[1]), "+f"(c[2]), "+f"(c[3])
        : "r"(a[0]), "r"(a[1]), "r"(a[2]), "r"(a[3]), "r"(b0), "r"(b1));
}

// ===================== GEMM config =====================
static constexpr int BM = 128, BN = 128, BK = 32, STAGES = 4, NTHREADS = 256;
static constexpr int A_STAGE_BYTES = BM * BK * 2;                   // 8192
static constexpr int B_STAGE_BYTES = BN * BK * 2;                   // 8192
static constexpr int STAGE_BYTES   = A_STAGE_BYTES + B_STAGE_BYTES; // 16384
static constexpr int SMEM_BIAS     = 0;
static constexpr int SMEM_TILES    = 1024;
static constexpr int SMEM_TOTAL    = SMEM_TILES + STAGES * STAGE_BYTES; // 66560

// D[m,n] = sum_k A[m,k] * BT[n*ldb + k] (+ bias[n]) (+ Cadd) (optional ReLU)
// out_mode: 0 = fp16 D, 1 = fp32 D.  cadd_mode: 0 none, 1 fp16, 2 fp32.
// A K-split: k < ksplit -> A0 (lda0) else A1 (lda1, k-ksplit). ksplit % BK == 0.
__global__ void __launch_bounds__(NTHREADS, 2)
gemm_f16(const __half* __restrict__ A0, const __half* __restrict__ A1,
         int ksplit, int lda0, int lda1,
         const __half* __restrict__ BT, int ldb, const float* __restrict__ bias,
         const void* __restrict__ Cadd, int ldc, int cadd_mode,
         void* __restrict__ D, int out_mode, int N, int K, int do_relu)
{
    extern __shared__ char smem[];
    float* sb_bias = (float*)(smem + SMEM_BIAS);
    const uint32_t stile = smem_u32(smem) + SMEM_TILES;
    const int tid  = threadIdx.x;
    const int wid  = tid >> 5;
    const int lane = tid & 31;
    const int g    = lane >> 2;
    const int t    = lane & 3;
    const int m0 = blockIdx.y * BM;
    const int n0 = blockIdx.x * BN;
    const int warp_m = (wid >> 2) * 64;
    const int warp_n = (wid & 3) * 32;

    if (tid < BN) sb_bias[tid] = bias ? bias[n0 + tid] : 0.f;

    const int KB = K / BK;

    auto load_stage = [&](int kb) {
        const int s = kb & (STAGES - 1);
        const int k0 = kb * BK;
        const uint32_t a_base = stile + s * STAGE_BYTES;
        const uint32_t b_base = a_base + A_STAGE_BYTES;
        #pragma unroll
        for (int j = 0; j < 2; j++) {
            int idx = tid + j * NTHREADS;
            int row = idx >> 2;
            int c   = idx & 3;
            int kg  = k0 + (c << 3);
            const __half* src = (kg < ksplit)
                ? (A0 + (size_t)(m0 + row) * lda0 + kg)
                : (A1 + (size_t)(m0 + row) * lda1 + (kg - ksplit));
            uint32_t dst = a_base + swz64((uint32_t)(row * 64 + (c << 4)));
            CP_ASYNC16(dst, src);
        }
        #pragma unroll
        for (int j = 0; j < 2; j++) {
            int idx = tid + j * NTHREADS;
            int row = idx >> 2;
            int c   = idx & 3;
            const __half* src = BT + (size_t)(n0 + row) * ldb + k0 + (c << 3);
            uint32_t dst = b_base + swz64((uint32_t)(row * 64 + (c << 4)));
            CP_ASYNC16(dst, src);
        }
        CP_ASYNC_COMMIT();
    };

    float acc[4][4][4];
    #pragma unroll
    for (int mt = 0; mt < 4; mt++)
        #pragma unroll
        for (int nt = 0; nt < 4; nt++)
            #pragma unroll
            for (int r = 0; r < 4; r++) acc[mt][nt][r] = 0.f;

    const int lm_row = (lane & 8) + (lane & 7);
    const int lm_k   = (lane & 16) >> 1;

    load_stage(0); load_stage(1); load_stage(2);

    for (int kb = 0; kb < KB; kb++) {
        if (kb < KB - 3) { CP_ASYNC_WAIT(2); } else { CP_ASYNC_WAIT(0); }
        __syncthreads();
        if (kb + 3 < KB) load_stage(kb + 3);

        const int s = kb & (STAGES - 1);
        const uint32_t As = stile + s * STAGE_BYTES;
        const uint32_t Bs = As + A_STAGE_BYTES;

        #pragma unroll
        for (int ks = 0; ks < 2; ks++) {
            const int kk = ks * 16;
            uint32_t am[4][4], bm[2][4];
            #pragma unroll
            for (int mt = 0; mt < 4; mt++) {
                int row = warp_m + mt * 16 + lm_row;
                ldmatrix_x4(am[mt], As + swz64((uint32_t)(row * 64 + (kk + lm_k) * 2)));
            }
            #pragma unroll
            for (int pr = 0; pr < 2; pr++) {
                int row = warp_n + pr * 16 + lm_row;
                ldmatrix_x4(bm[pr], Bs + swz64((uint32_t)(row * 64 + (kk + lm_k) * 2)));
            }
            #pragma unroll
            for (int mt = 0; mt < 4; mt++)
                #pragma unroll
                for (int nt = 0; nt < 4; nt++)
                    mma_f16(acc[mt][nt], am[mt], bm[nt >> 1][nt & 1], bm[nt >> 1][(nt & 1) + 2]);
        }
    }

    // epilogue
    #pragma unroll
    for (int mt = 0; mt < 4; mt++) {
        const int row = m0 + warp_m + mt * 16 + g;
        #pragma unroll
        for (int nt = 0; nt < 4; nt++) {
            const int cb = warp_n + nt * 8 + t * 2;
            const int col = n0 + cb;
            float b0 = sb_bias[cb], b1 = sb_bias[cb + 1];
            float2 v0 = make_float2(acc[mt][nt][0] + b0, acc[mt][nt][1] + b1);
            float2 v1 = make_float2(acc[mt][nt][2] + b0, acc[mt][nt][3] + b1);
            if (cadd_mode == 1) {
                const __half* C = (const __half*)Cadd;
                __half2 c0 = *reinterpret_cast<const __half2*>(C + (size_t)row * ldc + col);
                __half2 c1 = *reinterpret_cast<const __half2*>(C + (size_t)(row + 8) * ldc + col);
                v0.x += __half2float(c0.x); v0.y += __half2float(c0.y);
                v1.x += __half2float(c1.x); v1.y += __half2float(c1.y);
            } else if (cadd_mode == 2) {
                const float* C = (const float*)Cadd;
                float2 c0 = *reinterpret_cast<const float2*>(C + (size_t)row * ldc + col);
                float2 c1 = *reinterpret_cast<const float2*>(C + (size_t)(row + 8) * ldc + col);
                v0.x += c0.x; v0.y += c0.y;
                v1.x += c1.x; v1.y += c1.y;
            }
            if (do_relu) {
                v0.x = fmaxf(v0.x, 0.f); v0.y = fmaxf(v0.y, 0.f);
                v1.x = fmaxf(v1.x, 0.f); v1.y = fmaxf(v1.y, 0.f);
            }
            if (out_mode == 0) {
                __half* Dh = (__half*)D;
                *reinterpret_cast<__half2*>(Dh + (size_t)row * N + col)       = __floats2half2_rn(v0.x, v0.y);
                *reinterpret_cast<__half2*>(Dh + (size_t)(row + 8) * N + col) = __floats2half2_rn(v1.x, v1.y);
            } else {
                float* Df = (float*)D;
                *reinterpret_cast<float2*>(Df + (size_t)row * N + col)       = v0;
                *reinterpret_cast<float2*>(Df + (size_t)(row + 8) * N + col) = v1;
            }
        }
    }
}

// ===================== weight prep kernels =====================
// WT[n][k] = f16(w[k][n] * mask[n][k]);  mask stride = K (pass mask=nullptr to skip)
__global__ void transpose_mask(const float* __restrict__ w, const float* __restrict__ mask,
                               __half* __restrict__ wt, int K, int N)
{
    __shared__ float tile[32][33];
    const int k0 = blockIdx.x * 32, n0 = blockIdx.y * 32;
    const int tx = threadIdx.x, ty = threadIdx.y;
    #pragma unroll
    for (int j = 0; j < 32; j += 8)
        tile[ty + j][tx] = w[(size_t)(k0 + ty + j) * N + n0 + tx];
    __syncthreads();
    #pragma unroll
    for (int j = 0; j < 32; j += 8) {
        const int n = n0 + ty + j, k = k0 + tx;
        float v = tile[tx][ty + j];
        if (mask) v *= mask[(size_t)n * K + k];
        wt[(size_t)n * K + k] = __float2half_rn(v);
    }
}

// W1^T hi/lo split: w1s[n][k] = hi(W1[k,n]), w1s[n][1536+k] = lo. K=1536, N=512.
__global__ void transpose_split_w1(const float* __restrict__ w, __half* __restrict__ w1s,
                                   int K, int N)
{
    __shared__ float tile[32][33];
    const int k0 = blockIdx.x * 32, n0 = blockIdx.y * 32;
    const int tx = threadIdx.x, ty = threadIdx.y;
    #pragma unroll
    for (int j = 0; j < 32; j += 8)
        tile[ty + j][tx] = w[(size_t)(k0 + ty + j) * N + n0 + tx];
    __syncthreads();
    #pragma unroll
    for (int j = 0; j < 32; j += 8) {
        const int n = n0 + ty + j, k = k0 + tx;
        float v = tile[tx][ty + j];
        __half hi = __float2half_rn(v);
        __half lo = __float2half_rn(v - __half2float(hi));
        w1s[(size_t)n * (2 * K) + k]     = hi;
        w1s[(size_t)n * (2 * K) + K + k] = lo;
    }
}

// out[i][j] = f16(w[i][j] * mask[j][i]); w rows i (stride J), mask rows j (stride mstride)
__global__ void mask_apply_nt(const float* __restrict__ w, const float* __restrict__ mask,
                              int mstride, __half* __restrict__ out, int J)
{
    __shared__ float mt[32][33];
    const int i0 = blockIdx.y * 32, j0 = blockIdx.x * 32;
    const int tx = threadIdx.x, ty = threadIdx.y;
    #pragma unroll
    for (int jj = 0; jj < 32; jj += 8)
        mt[ty + jj][tx] = mask[(size_t)(j0 + ty + jj) * mstride + i0 + tx];
    __syncthreads();
    #pragma unroll
    for (int jj = 0; jj < 32; jj += 8) {
        const int i = i0 + ty + jj, j = j0 + tx;
        out[(size_t)i * J + j] = __float2half_rn(w[(size_t)i * J + j] * mt[tx][ty + jj]);
    }
}

// fp32 variant: out[i][j] = w[i][j] * mask[j][i]
__global__ void mask_apply_nt_f32(const float* __restrict__ w, const float* __restrict__ mask,
                                  int mstride, float* __restrict__ out, int J)
{
    __shared__ float mt[32][33];
    const int i0 = blockIdx.y * 32, j0 = blockIdx.x * 32;
    const int tx = threadIdx.x, ty = threadIdx.y;
    #pragma unroll
    for (int jj = 0; jj < 32; jj += 8)
        mt[ty + jj][tx] = mask[(size_t)(j0 + ty + jj) * mstride + i0 + tx];
    __syncthreads();
    #pragma unroll
    for (int jj = 0; jj < 32; jj += 8) {
        const int i = i0 + ty + jj, j = j0 + tx;
        out[(size_t)i * J + j] = w[(size_t)i * J + j] * mt[tx][ty + jj];
    }
}

// weffs[i][j] = lo, weffs[i][1536+j] = hi of weff32[i][j]
__global__ void split_hilo(const float* __restrict__ src, __half* __restrict__ dst, int J)
{
    const int i = blockIdx.y;
    const int j = blockIdx.x * blockDim.x + threadIdx.x;
    float v = src[(size_t)i * J + j];
    __half hi = __float2half_rn(v);
    __half lo = __float2half_rn(v - __half2float(hi));
    dst[(size_t)i * (2 * J) + j]     = lo;
    dst[(size_t)i * (2 * J) + J + j] = hi;
}

// bias_eff[n] = gpi_b[n] + sum_j gpe_b[j] * wt_gpi[n][1536+j]
__global__ void bias_eff_kernel(const __half* __restrict__ wt_gpi, const float* __restrict__ gpe_b,
                                const float* __restrict__ gpi_b, float* __restrict__ be)
{
    const int n = blockIdx.x * 8 + (threadIdx.x >> 5);
    const int lane = threadIdx.x & 31;
    const __half* row = wt_gpi + (size_t)n * DGPI_IN + DGPE_IN;
    float s = 0.f;
    for (int j = lane; j < DGPE_OUT; j += 32)
        s += __half2float(row[j]) * gpe_b[j];
    #pragma unroll
    for (int off = 16; off; off >>= 1) s += __shfl_xor_sync(0xffffffffu, s, off);
    if (lane == 0) be[n] = gpi_b[n] + s;
}

// bias_full[n] = b1[n] + sum_j bias_eff[j] * w1[j*U3 + n]   (one block, 512 threads)
__global__ void bias_full_kernel(const float* __restrict__ be, const float* __restrict__ w1,
                                 const float* __restrict__ b1, float* __restrict__ bf)
{
    const int n = threadIdx.x;
    float s = b1[n];
    for (int j = 0; j < DGPI_OUT; j++)
        s += be[j] * w1[(size_t)j * U3 + n];
    bf[n] = s;
}

// ===================== x fp32 -> fp16 =====================
__global__ void convert_f2h(const float* __restrict__ src, __half* __restrict__ dst, int n)
{
    int i = (blockIdx.x * blockDim.x + threadIdx.x) * 4;
    if (i < n) {
        float4 v = *reinterpret_cast<const float4*>(src + i);
        *reinterpret_cast<__half2*>(dst + i)     = __floats2half2_rn(v.x, v.y);
        *reinterpret_cast<__half2*>(dst + i + 2) = __floats2half2_rn(v.z, v.w);
    }
}

// ===================== final skinny layer: out = relu(h @ w3 + b3), N=6 =====================
__global__ void final_layer(const __half* __restrict__ h, const float* __restrict__ w3,
                            const float* __restrict__ b3, float* __restrict__ out)
{
    __shared__ float sw[U3 * ACT];
    __shared__ float sbb[ACT];
    const int tid = threadIdx.x;
    for (int i = tid; i < U3 * ACT; i += blockDim.x) sw[i] = w3[i];
    if (tid < ACT) sbb[tid] = b3[tid];
    __syncthreads();
    const int wid = tid >> 5, lane = tid & 31;
    const int row = blockIdx.x * (blockDim.x >> 5) + wid;
    const __half* hr = h + (size_t)row * U3;
    float acc[ACT] = {0.f, 0.f, 0.f, 0.f, 0.f, 0.f};
    for (int k0 = lane * 2; k0 < U3; k0 += 64) {
        __half2 hv = *reinterpret_cast<const __half2*>(hr + k0);
        float x0 = __half2float(hv.x), x1 = __half2float(hv.y);
        #pragma unroll
        for (int n = 0; n < ACT; n++)
            acc[n] += x0 * sw[k0 * ACT + n] + x1 * sw[(k0 + 1) * ACT + n];
    }
    #pragma unroll
    for (int n = 0; n < ACT; n++)
        #pragma unroll
        for (int off = 16; off; off >>= 1)
            acc[n] += __shfl_xor_sync(0xffffffffu, acc[n], off);
    if (lane < ACT) out[(size_t)row * ACT + lane] = fmaxf(acc[lane] + sbb[lane], 0.f);
}

// ===================== launch =====================
extern "C" void kernel_launch(void* const* d_in, const int* in_sizes, int n_in,
                              void* d_out, int out_size)
{
    const float* x        = (const float*)d_in[0];
    const float* gpe_mask = (const float*)d_in[1];
    const float* gpe_w    = (const float*)d_in[2];
    const float* gpe_b    = (const float*)d_in[3];
    const float* gpi_mask = (const float*)d_in[4];
    const float* gpi_w    = (const float*)d_in[5];
    const float* gpi_b    = (const float*)d_in[6];
    const float* w1       = (const float*)d_in[7];
    const float* b1       = (const float*)d_in[8];
    const float* w2       = (const float*)d_in[9];
    const float* b2       = (const float*)d_in[10];
    const float* w3       = (const float*)d_in[11];
    const float* b3       = (const float*)d_in[12];
    float* out = (float*)d_out;

    __half *xh, *wt_gpi, *wm_gpe, *weffs, *w1s, *wfull_h, *wt_w2, *h1, *h2;
    float *wx32, *weff32, *wfull32, *bias_eff, *bias_full;
    cudaGetSymbolAddress((void**)&xh,        g_xh);
    cudaGetSymbolAddress((void**)&wt_gpi,    g_wt_gpi);
    cudaGetSymbolAddress((void**)&wm_gpe,    g_wm_gpe);
    cudaGetSymbolAddress((void**)&wx32,      g_wx32);
    cudaGetSymbolAddress((void**)&weff32,    g_weff32);
    cudaGetSymbolAddress((void**)&weffs,     g_weffs);
    cudaGetSymbolAddress((void**)&w1s,       g_w1s);
    cudaGetSymbolAddress((void**)&wfull32,   g_wfull32);
    cudaGetSymbolAddress((void**)&wfull_h,   g_wfull_h);
    cudaGetSymbolAddress((void**)&bias_eff,  g_bias_eff);
    cudaGetSymbolAddress((void**)&bias_full, g_bias_full);
    cudaGetSymbolAddress((void**)&wt_w2,     g_wt_w2);
    cudaGetSymbolAddress((void**)&h1,        g_h1);
    cudaGetSymbolAddress((void**)&h2,        g_h2);

    cudaFuncSetAttribute(gemm_f16, cudaFuncAttributeMaxDynamicSharedMemorySize, SMEM_TOTAL);

    const dim3 tb(32, 8);
    const int nx = BATCH * DGPE_IN;
    convert_f2h<<<(nx / 4 + 255) / 256, 256>>>(x, xh, nx);

    // masked gpi W^T fp16 [j][3072]
    transpose_mask<<<dim3(DGPI_IN / 32, DGPI_OUT / 32), tb>>>(gpi_w, gpi_mask, wt_gpi, DGPI_IN, DGPI_OUT);
    // masked gpe W non-transposed fp16 [i][1536]
    mask_apply_nt<<<dim3(DGPE_OUT / 32, DGPE_IN / 32), tb>>>(gpe_w, gpe_mask, DGPE_IN, wm_gpe, DGPE_OUT);
    // Wx^T fp32 [i][j]: first 1536 rows of gpi_w, masked (mask stride 3072)
    mask_apply_nt_f32<<<dim3(DGPI_OUT / 32, DGPE_IN / 32), tb>>>(gpi_w, gpi_mask, DGPI_IN, wx32, DGPI_OUT);
    // W2^T fp16
    transpose_mask<<<dim3(U3 / 32, U3 / 32), tb>>>(w2, nullptr, wt_w2, U3, U3);
    // W1^T hi/lo split [n][hi|lo]
    transpose_split_w1<<<dim3(DGPI_OUT / 32, U3 / 32), tb>>>(w1, w1s, DGPI_OUT, U3);
    // biases
    bias_eff_kernel<<<DGPI_OUT / 8, 256>>>(wt_gpi, gpe_b, gpi_b, bias_eff);
    bias_full_kernel<<<1, U3>>>(bias_eff, w1, b1, bias_full);

    // W_eff^T fp32 [i][j] = Wgpe@Wg (fp16 GEMM, fp32 out) + Wx^T (fp32 Cadd)   (7.2 GF)
    gemm_f16<<<dim3(DGPI_OUT / BN, DGPE_IN / BM), NTHREADS, SMEM_TOTAL>>>(
        wm_gpe, wm_gpe, DGPE_OUT, DGPE_OUT, DGPE_OUT,
        wt_gpi + DGPE_IN, DGPI_IN, nullptr,
        wx32, DGPI_OUT, 2, weff32, 1, DGPI_OUT, DGPE_OUT, 0);
    // split W_eff^T -> [i][lo|hi]
    split_hilo<<<dim3(DGPI_OUT / 256, DGPE_IN), 256>>>(weff32, weffs, DGPI_OUT);

    // W_full pass a: hi@hi -> fp32 [n][i]   (2.4 GF)
    gemm_f16<<<dim3(DGPE_IN / BN, U3 / BM), NTHREADS, SMEM_TOTAL>>>(
        w1s, w1s, DGPI_OUT, 2 * DGPI_OUT, 2 * DGPI_OUT,
        weffs + DGPI_OUT, 2 * DGPI_OUT, nullptr,
        nullptr, 0, 0, wfull32, 1, DGPE_IN, DGPI_OUT, 0);
    // W_full pass b: hi@lo + lo@hi (K-split 3072) + pass-a fp32 Cadd -> fp16   (4.8 GF)
    gemm_f16<<<dim3(DGPE_IN / BN, U3 / BM), NTHREADS, SMEM_TOTAL>>>(
        w1s, w1s + DGPI_OUT, DGPI_OUT, 2 * DGPI_OUT, 2 * DGPI_OUT,
        weffs, 2 * DGPI_OUT, nullptr,
        wfull32, DGPE_IN, 2, wfull_h, 0, DGPE_IN, 2 * DGPI_OUT, 0);

    // h1 = relu(x @ W_full + bias_full)   (25.8 GF)
    gemm_f16<<<dim3(U3 / BN, BATCH / BM), NTHREADS, SMEM_TOTAL>>>(
        xh, xh, DGPE_IN, DGPE_IN, DGPE_IN,
        wfull_h, DGPE_IN, bias_full,
        nullptr, 0, 0, h1, 0, U3, DGPE_IN, 1);
    // h2 = relu(h1 @ w2 + b2)   (8.6 GF)
    gemm_f16<<<dim3(U3 / BN, BATCH / BM), NTHREADS, SMEM_TOTAL>>>(
        h1, h1, U3, U3, U3,
        wt_w2, U3, b2,
        nullptr, 0, 0, h2, 0, U3, U3, 1);
    // out = relu(h2 @ w3 + b3)
    final_layer<<<BATCH / 8, 256>>>(h2, w3, b3, out);
}

// round 8
// speedup vs baseline: 5.6206x; 1.1891x over previous
#include <cuda_runtime.h>
#include <cuda_fp16.h>
#include <cstdint>

// ===================== problem dims =====================
static constexpr int BATCH    = 16384;
static constexpr int DGPE_IN  = 1536;
static constexpr int DGPE_OUT = 1536;
static constexpr int DGPI_IN  = 3072;
static constexpr int DGPI_OUT = 1536;
static constexpr int U3       = 512;
static constexpr int ACT      = 6;

// ===================== device scratch (no cudaMalloc allowed) =====================
__device__ __half g_xh     [(size_t)BATCH * DGPE_IN];      // x as fp16
__device__ __half g_wt_gpi [DGPI_OUT * DGPI_IN];           // [j][k'] masked gpi W^T fp16
__device__ __half g_wm_gpe [DGPE_IN * DGPE_OUT];           // [i][k] masked gpe W (non-transposed)
__device__ float  g_wx32   [DGPE_IN * DGPI_OUT];           // [i][j] masked Wx (fp32, exact)
__device__ float  g_weff32 [DGPE_IN * DGPI_OUT];           // [i][j] W_eff^T fp32
__device__ __half g_weffs  [(size_t)DGPE_IN * 3 * DGPI_OUT]; // [i][ hi | hi | lo ]
__device__ __half g_w1s    [U3 * 2 * DGPI_OUT];            // [n][ hi | lo ]
__device__ __half g_wfull_h[U3 * DGPE_IN];                 // [n][i] fp16 final
__device__ float  g_bias_eff[DGPI_OUT];
__device__ float  g_bias_full[U3];
__device__ __half g_wt_w2  [U3 * U3];
__device__ __half g_h1[(size_t)BATCH * U3];
__device__ __half g_h2[(size_t)BATCH * U3];

// ===================== helpers =====================
__device__ __forceinline__ uint32_t smem_u32(const void* p) {
    return (uint32_t)__cvta_generic_to_shared(p);
}
#define CP_ASYNC16(dst, src) \
    asm volatile("cp.async.cg.shared.global [%0], [%1], 16;\n" :: "r"(dst), "l"(src))
#define CP_ASYNC_COMMIT() asm volatile("cp.async.commit_group;\n" ::: "memory")
#define CP_ASYNC_WAIT(n)  asm volatile("cp.async.wait_group %0;\n" :: "n"(n) : "memory")

__device__ __forceinline__ uint32_t swz64(uint32_t byte_off) {
    return byte_off ^ ((byte_off >> 3) & 0x30);
}

__device__ __forceinline__ void ldmatrix_x4(uint32_t r[4], uint32_t addr) {
    asm volatile("ldmatrix.sync.aligned.m8n8.x4.shared.b16 {%0,%1,%2,%3}, [%4];"
                 : "=r"(r[0]), "=r"(r[1]), "=r"(r[2]), "=r"(r[3]) : "r"(addr));
}

__device__ __forceinline__ void mma_f16(float c[4], const uint32_t a[4],
                                        uint32_t b0, uint32_t b1) {
    asm volatile(
        "mma.sync.aligned.m16n8k16.row.col.f32.f16.f16.f32 "
        "{%0,%1,%2,%3}, {%4,%5,%6,%7}, {%8,%9}, {%0,%1,%2,%3};"
        : "+f"(c[0]), "+f"(c[1]), "+f"(c[2]), "+f"(c[3])
        : "r"(a[0]), "r"(a[1]), "r"(a[2]), "r"(a[3]), "r"(b0), "r"(b1));
}

// ===================== GEMM config =====================
static constexpr int BM = 128, BN = 128, BK = 32, STAGES = 4, NTHREADS = 256;
static constexpr int A_STAGE_BYTES = BM * BK * 2;
static constexpr int B_STAGE_BYTES = BN * BK * 2;
static constexpr int STAGE_BYTES   = A_STAGE_BYTES + B_STAGE_BYTES;
static constexpr int SMEM_BIAS     = 0;
static constexpr int SMEM_TILES    = 1024;
static constexpr int SMEM_TOTAL    = SMEM_TILES + STAGES * STAGE_BYTES; // 66560

// D[m,n] = sum_k A[m,k] * BT[n*ldb + k] (+ bias[n]) (+ Cadd) (optional ReLU)
// out_mode: 0 = fp16 D, 1 = fp32 D.  cadd_mode: 0 none, 1 fp16, 2 fp32.
// A K-split: k < ksplit -> A0 (lda0) else A1 (lda1, k-ksplit). ksplit % BK == 0.
__global__ void __launch_bounds__(NTHREADS, 2)
gemm_f16(const __half* __restrict__ A0, const __half* __restrict__ A1,
         int ksplit, int lda0, int lda1,
         const __half* __restrict__ BT, int ldb, const float* __restrict__ bias,
         const void* __restrict__ Cadd, int ldc, int cadd_mode,
         void* __restrict__ D, int out_mode, int N, int K, int do_relu)
{
    extern __shared__ char smem[];
    float* sb_bias = (float*)(smem + SMEM_BIAS);
    const uint32_t stile = smem_u32(smem) + SMEM_TILES;
    const int tid  = threadIdx.x;
    const int wid  = tid >> 5;
    const int lane = tid & 31;
    const int g    = lane >> 2;
    const int t    = lane & 3;
    const int m0 = blockIdx.y * BM;
    const int n0 = blockIdx.x * BN;
    const int warp_m = (wid >> 2) * 64;
    const int warp_n = (wid & 3) * 32;

    if (tid < BN) sb_bias[tid] = bias ? bias[n0 + tid] : 0.f;

    const int KB = K / BK;

    auto load_stage = [&](int kb) {
        const int s = kb & (STAGES - 1);
        const int k0 = kb * BK;
        const uint32_t a_base = stile + s * STAGE_BYTES;
        const uint32_t b_base = a_base + A_STAGE_BYTES;
        #pragma unroll
        for (int j = 0; j < 2; j++) {
            int idx = tid + j * NTHREADS;
            int row = idx >> 2;
            int c   = idx & 3;
            int kg  = k0 + (c << 3);
            const __half* src = (kg < ksplit)
                ? (A0 + (size_t)(m0 + row) * lda0 + kg)
                : (A1 + (size_t)(m0 + row) * lda1 + (kg - ksplit));
            uint32_t dst = a_base + swz64((uint32_t)(row * 64 + (c << 4)));
            CP_ASYNC16(dst, src);
        }
        #pragma unroll
        for (int j = 0; j < 2; j++) {
            int idx = tid + j * NTHREADS;
            int row = idx >> 2;
            int c   = idx & 3;
            const __half* src = BT + (size_t)(n0 + row) * ldb + k0 + (c << 3);
            uint32_t dst = b_base + swz64((uint32_t)(row * 64 + (c << 4)));
            CP_ASYNC16(dst, src);
        }
        CP_ASYNC_COMMIT();
    };

    float acc[4][4][4];
    #pragma unroll
    for (int mt = 0; mt < 4; mt++)
        #pragma unroll
        for (int nt = 0; nt < 4; nt++)
            #pragma unroll
            for (int r = 0; r < 4; r++) acc[mt][nt][r] = 0.f;

    const int lm_row = (lane & 8) + (lane & 7);
    const int lm_k   = (lane & 16) >> 1;

    load_stage(0); load_stage(1); load_stage(2);

    for (int kb = 0; kb < KB; kb++) {
        if (kb < KB - 3) { CP_ASYNC_WAIT(2); } else { CP_ASYNC_WAIT(0); }
        __syncthreads();
        if (kb + 3 < KB) load_stage(kb + 3);

        const int s = kb & (STAGES - 1);
        const uint32_t As = stile + s * STAGE_BYTES;
        const uint32_t Bs = As + A_STAGE_BYTES;

        #pragma unroll
        for (int ks = 0; ks < 2; ks++) {
            const int kk = ks * 16;
            uint32_t am[4][4], bm[2][4];
            #pragma unroll
            for (int mt = 0; mt < 4; mt++) {
                int row = warp_m + mt * 16 + lm_row;
                ldmatrix_x4(am[mt], As + swz64((uint32_t)(row * 64 + (kk + lm_k) * 2)));
            }
            #pragma unroll
            for (int pr = 0; pr < 2; pr++) {
                int row = warp_n + pr * 16 + lm_row;
                ldmatrix_x4(bm[pr], Bs + swz64((uint32_t)(row * 64 + (kk + lm_k) * 2)));
            }
            #pragma unroll
            for (int mt = 0; mt < 4; mt++)
                #pragma unroll
                for (int nt = 0; nt < 4; nt++)
                    mma_f16(acc[mt][nt], am[mt], bm[nt >> 1][nt & 1], bm[nt >> 1][(nt & 1) + 2]);
        }
    }

    // epilogue
    #pragma unroll
    for (int mt = 0; mt < 4; mt++) {
        const int row = m0 + warp_m + mt * 16 + g;
        #pragma unroll
        for (int nt = 0; nt < 4; nt++) {
            const int cb = warp_n + nt * 8 + t * 2;
            const int col = n0 + cb;
            float b0 = sb_bias[cb], b1 = sb_bias[cb + 1];
            float2 v0 = make_float2(acc[mt][nt][0] + b0, acc[mt][nt][1] + b1);
            float2 v1 = make_float2(acc[mt][nt][2] + b0, acc[mt][nt][3] + b1);
            if (cadd_mode == 1) {
                const __half* C = (const __half*)Cadd;
                __half2 c0 = *reinterpret_cast<const __half2*>(C + (size_t)row * ldc + col);
                __half2 c1 = *reinterpret_cast<const __half2*>(C + (size_t)(row + 8) * ldc + col);
                v0.x += __half2float(c0.x); v0.y += __half2float(c0.y);
                v1.x += __half2float(c1.x); v1.y += __half2float(c1.y);
            } else if (cadd_mode == 2) {
                const float* C = (const float*)Cadd;
                float2 c0 = *reinterpret_cast<const float2*>(C + (size_t)row * ldc + col);
                float2 c1 = *reinterpret_cast<const float2*>(C + (size_t)(row + 8) * ldc + col);
                v0.x += c0.x; v0.y += c0.y;
                v1.x += c1.x; v1.y += c1.y;
            }
            if (do_relu) {
                v0.x = fmaxf(v0.x, 0.f); v0.y = fmaxf(v0.y, 0.f);
                v1.x = fmaxf(v1.x, 0.f); v1.y = fmaxf(v1.y, 0.f);
            }
            if (out_mode == 0) {
                __half* Dh = (__half*)D;
                *reinterpret_cast<__half2*>(Dh + (size_t)row * N + col)       = __floats2half2_rn(v0.x, v0.y);
                *reinterpret_cast<__half2*>(Dh + (size_t)(row + 8) * N + col) = __floats2half2_rn(v1.x, v1.y);
            } else {
                float* Df = (float*)D;
                *reinterpret_cast<float2*>(Df + (size_t)row * N + col)       = v0;
                *reinterpret_cast<float2*>(Df + (size_t)(row + 8) * N + col) = v1;
            }
        }
    }
}

// ===================== weight prep kernels =====================
__global__ void transpose_mask(const float* __restrict__ w, const float* __restrict__ mask,
                               __half* __restrict__ wt, int K, int N)
{
    __shared__ float tile[32][33];
    const int k0 = blockIdx.x * 32, n0 = blockIdx.y * 32;
    const int tx = threadIdx.x, ty = threadIdx.y;
    #pragma unroll
    for (int j = 0; j < 32; j += 8)
        tile[ty + j][tx] = w[(size_t)(k0 + ty + j) * N + n0 + tx];
    __syncthreads();
    #pragma unroll
    for (int j = 0; j < 32; j += 8) {
        const int n = n0 + ty + j, k = k0 + tx;
        float v = tile[tx][ty + j];
        if (mask) v *= mask[(size_t)n * K + k];
        wt[(size_t)n * K + k] = __float2half_rn(v);
    }
}

// W1^T hi/lo split: w1s[n][k] = hi(W1[k,n]), w1s[n][K+k] = lo. lda = 2K.
__global__ void transpose_split_w1(const float* __restrict__ w, __half* __restrict__ w1s,
                                   int K, int N)
{
    __shared__ float tile[32][33];
    const int k0 = blockIdx.x * 32, n0 = blockIdx.y * 32;
    const int tx = threadIdx.x, ty = threadIdx.y;
    #pragma unroll
    for (int j = 0; j < 32; j += 8)
        tile[ty + j][tx] = w[(size_t)(k0 + ty + j) * N + n0 + tx];
    __syncthreads();
    #pragma unroll
    for (int j = 0; j < 32; j += 8) {
        const int n = n0 + ty + j, k = k0 + tx;
        float v = tile[tx][ty + j];
        __half hi = __float2half_rn(v);
        __half lo = __float2half_rn(v - __half2float(hi));
        w1s[(size_t)n * (2 * K) + k]     = hi;
        w1s[(size_t)n * (2 * K) + K + k] = lo;
    }
}

__global__ void mask_apply_nt(const float* __restrict__ w, const float* __restrict__ mask,
                              int mstride, __half* __restrict__ out, int J)
{
    __shared__ float mt[32][33];
    const int i0 = blockIdx.y * 32, j0 = blockIdx.x * 32;
    const int tx = threadIdx.x, ty = threadIdx.y;
    #pragma unroll
    for (int jj = 0; jj < 32; jj += 8)
        mt[ty + jj][tx] = mask[(size_t)(j0 + ty + jj) * mstride + i0 + tx];
    __syncthreads();
    #pragma unroll
    for (int jj = 0; jj < 32; jj += 8) {
        const int i = i0 + ty + jj, j = j0 + tx;
        out[(size_t)i * J + j] = __float2half_rn(w[(size_t)i * J + j] * mt[tx][ty + jj]);
    }
}

__global__ void mask_apply_nt_f32(const float* __restrict__ w, const float* __restrict__ mask,
                                  int mstride, float* __restrict__ out, int J)
{
    __shared__ float mt[32][33];
    const int i0 = blockIdx.y * 32, j0 = blockIdx.x * 32;
    const int tx = threadIdx.x, ty = threadIdx.y;
    #pragma unroll
    for (int jj = 0; jj < 32; jj += 8)
        mt[ty + jj][tx] = mask[(size_t)(j0 + ty + jj) * mstride + i0 + tx];
    __syncthreads();
    #pragma unroll
    for (int jj = 0; jj < 32; jj += 8) {
        const int i = i0 + ty + jj, j = j0 + tx;
        out[(size_t)i * J + j] = w[(size_t)i * J + j] * mt[tx][ty + jj];
    }
}

// weffs[i][ j ]=hi, [J+j]=hi, [2J+j]=lo  (3-segment layout for single-pass hi/lo GEMM)
__global__ void split_hilo3(const float* __restrict__ src, __half* __restrict__ dst, int J)
{
    const int i = blockIdx.y;
    const int j = blockIdx.x * blockDim.x + threadIdx.x;
    float v = src[(size_t)i * J + j];
    __half hi = __float2half_rn(v);
    __half lo = __float2half_rn(v - __half2float(hi));
    const size_t base = (size_t)i * (3 * J);
    dst[base + j]         = hi;
    dst[base + J + j]     = hi;
    dst[base + 2 * J + j] = lo;
}

__global__ void bias_eff_kernel(const __half* __restrict__ wt_gpi, const float* __restrict__ gpe_b,
                                const float* __restrict__ gpi_b, float* __restrict__ be)
{
    const int n = blockIdx.x * 8 + (threadIdx.x >> 5);
    const int lane = threadIdx.x & 31;
    const __half* row = wt_gpi + (size_t)n * DGPI_IN + DGPE_IN;
    float s = 0.f;
    for (int j = lane; j < DGPE_OUT; j += 32)
        s += __half2float(row[j]) * gpe_b[j];
    #pragma unroll
    for (int off = 16; off; off >>= 1) s += __shfl_xor_sync(0xffffffffu, s, off);
    if (lane == 0) be[n] = gpi_b[n] + s;
}

__global__ void bias_full_kernel(const float* __restrict__ be, const float* __restrict__ w1,
                                 const float* __restrict__ b1, float* __restrict__ bf)
{
    const int n = threadIdx.x;
    float s = b1[n];
    for (int j = 0; j < DGPI_OUT; j++)
        s += be[j] * w1[(size_t)j * U3 + n];
    bf[n] = s;
}

__global__ void convert_f2h(const float* __restrict__ src, __half* __restrict__ dst, int n)
{
    int i = (blockIdx.x * blockDim.x + threadIdx.x) * 4;
    if (i < n) {
        float4 v = *reinterpret_cast<const float4*>(src + i);
        *reinterpret_cast<__half2*>(dst + i)     = __floats2half2_rn(v.x, v.y);
        *reinterpret_cast<__half2*>(dst + i + 2) = __floats2half2_rn(v.z, v.w);
    }
}

__global__ void final_layer(const __half* __restrict__ h, const float* __restrict__ w3,
                            const float* __restrict__ b3, float* __restrict__ out)
{
    __shared__ float sw[U3 * ACT];
    __shared__ float sbb[ACT];
    const int tid = threadIdx.x;
    for (int i = tid; i < U3 * ACT; i += blockDim.x) sw[i] = w3[i];
    if (tid < ACT) sbb[tid] = b3[tid];
    __syncthreads();
    const int wid = tid >> 5, lane = tid & 31;
    const int row = blockIdx.x * (blockDim.x >> 5) + wid;
    const __half* hr = h + (size_t)row * U3;
    float acc[ACT] = {0.f, 0.f, 0.f, 0.f, 0.f, 0.f};
    for (int k0 = lane * 2; k0 < U3; k0 += 64) {
        __half2 hv = *reinterpret_cast<const __half2*>(hr + k0);
        float x0 = __half2float(hv.x), x1 = __half2float(hv.y);
        #pragma unroll
        for (int n = 0; n < ACT; n++)
            acc[n] += x0 * sw[k0 * ACT + n] + x1 * sw[(k0 + 1) * ACT + n];
    }
    #pragma unroll
    for (int n = 0; n < ACT; n++)
        #pragma unroll
        for (int off = 16; off; off >>= 1)
            acc[n] += __shfl_xor_sync(0xffffffffu, acc[n], off);
    if (lane < ACT) out[(size_t)row * ACT + lane] = fmaxf(acc[lane] + sbb[lane], 0.f);
}

// ===================== launch =====================
extern "C" void kernel_launch(void* const* d_in, const int* in_sizes, int n_in,
                              void* d_out, int out_size)
{
    const float* x        = (const float*)d_in[0];
    const float* gpe_mask = (const float*)d_in[1];
    const float* gpe_w    = (const float*)d_in[2];
    const float* gpe_b    = (const float*)d_in[3];
    const float* gpi_mask = (const float*)d_in[4];
    const float* gpi_w    = (const float*)d_in[5];
    const float* gpi_b    = (const float*)d_in[6];
    const float* w1       = (const float*)d_in[7];
    const float* b1       = (const float*)d_in[8];
    const float* w2       = (const float*)d_in[9];
    const float* b2       = (const float*)d_in[10];
    const float* w3       = (const float*)d_in[11];
    const float* b3       = (const float*)d_in[12];
    float* out = (float*)d_out;

    __half *xh, *wt_gpi, *wm_gpe, *weffs, *w1s, *wfull_h, *wt_w2, *h1, *h2;
    float *wx32, *weff32, *bias_eff, *bias_full;
    cudaGetSymbolAddress((void**)&xh,        g_xh);
    cudaGetSymbolAddress((void**)&wt_gpi,    g_wt_gpi);
    cudaGetSymbolAddress((void**)&wm_gpe,    g_wm_gpe);
    cudaGetSymbolAddress((void**)&wx32,      g_wx32);
    cudaGetSymbolAddress((void**)&weff32,    g_weff32);
    cudaGetSymbolAddress((void**)&weffs,     g_weffs);
    cudaGetSymbolAddress((void**)&w1s,       g_w1s);
    cudaGetSymbolAddress((void**)&wfull_h,   g_wfull_h);
    cudaGetSymbolAddress((void**)&bias_eff,  g_bias_eff);
    cudaGetSymbolAddress((void**)&bias_full, g_bias_full);
    cudaGetSymbolAddress((void**)&wt_w2,     g_wt_w2);
    cudaGetSymbolAddress((void**)&h1,        g_h1);
    cudaGetSymbolAddress((void**)&h2,        g_h2);

    cudaFuncSetAttribute(gemm_f16, cudaFuncAttributeMaxDynamicSharedMemorySize, SMEM_TOTAL);

    // One-time stream/event creation (host-side resources; identical device work
    // is enqueued on every call, so determinism and graph-capturability hold).
    static cudaStream_t sA = nullptr, sB = nullptr, sC = nullptr;
    static cudaEvent_t evRoot, evGpi, evWx, evW1s, evW2, evWfull, evBias;
    if (sA == nullptr) {
        cudaStreamCreateWithFlags(&sA, cudaStreamNonBlocking);
        cudaStreamCreateWithFlags(&sB, cudaStreamNonBlocking);
        cudaStreamCreateWithFlags(&sC, cudaStreamNonBlocking);
        cudaEventCreateWithFlags(&evRoot,  cudaEventDisableTiming);
        cudaEventCreateWithFlags(&evGpi,   cudaEventDisableTiming);
        cudaEventCreateWithFlags(&evWx,    cudaEventDisableTiming);
        cudaEventCreateWithFlags(&evW1s,   cudaEventDisableTiming);
        cudaEventCreateWithFlags(&evW2,    cudaEventDisableTiming);
        cudaEventCreateWithFlags(&evWfull, cudaEventDisableTiming);
        cudaEventCreateWithFlags(&evBias,  cudaEventDisableTiming);
    }

    const dim3 tb(32, 8);
    const int nx = BATCH * DGPE_IN;

    // ---- fork ----
    cudaEventRecord(evRoot, 0);
    cudaStreamWaitEvent(sA, evRoot, 0);
    cudaStreamWaitEvent(sB, evRoot, 0);
    cudaStreamWaitEvent(sC, evRoot, 0);

    // L (legacy stream): the big independent x conversion, overlapped with all prep
    convert_f2h<<<(nx / 4 + 255) / 256, 256>>>(x, xh, nx);

    // sA: gpi transpose -> biases
    transpose_mask<<<dim3(DGPI_IN / 32, DGPI_OUT / 32), tb, 0, sA>>>(gpi_w, gpi_mask, wt_gpi, DGPI_IN, DGPI_OUT);
    cudaEventRecord(evGpi, sA);
    bias_eff_kernel<<<DGPI_OUT / 8, 256, 0, sA>>>(wt_gpi, gpe_b, gpi_b, bias_eff);
    bias_full_kernel<<<1, U3, 0, sA>>>(bias_eff, w1, b1, bias_full);
    cudaEventRecord(evBias, sA);

    // sC: wx32 (needed by W_eff), then w1 split and w2 transpose
    mask_apply_nt_f32<<<dim3(DGPI_OUT / 32, DGPE_IN / 32), tb, 0, sC>>>(gpi_w, gpi_mask, DGPI_IN, wx32, DGPI_OUT);
    cudaEventRecord(evWx, sC);
    transpose_split_w1<<<dim3(DGPI_OUT / 32, U3 / 32), tb, 0, sC>>>(w1, w1s, DGPI_OUT, U3);
    cudaEventRecord(evW1s, sC);
    transpose_mask<<<dim3(U3 / 32, U3 / 32), tb, 0, sC>>>(w2, nullptr, wt_w2, U3, U3);
    cudaEventRecord(evW2, sC);

    // sB: gpe mask -> W_eff GEMM -> split -> single-pass W_full GEMM
    mask_apply_nt<<<dim3(DGPE_OUT / 32, DGPE_IN / 32), tb, 0, sB>>>(gpe_w, gpe_mask, DGPE_IN, wm_gpe, DGPE_OUT);
    cudaStreamWaitEvent(sB, evGpi, 0);
    cudaStreamWaitEvent(sB, evWx, 0);
    // W_eff^T fp32 [i][j] = Wgpe@Wg + Wx^T   (7.2 GF)
    gemm_f16<<<dim3(DGPI_OUT / BN, DGPE_IN / BM), NTHREADS, SMEM_TOTAL, sB>>>(
        wm_gpe, wm_gpe, DGPE_OUT, DGPE_OUT, DGPE_OUT,
        wt_gpi + DGPE_IN, DGPI_IN, nullptr,
        wx32, DGPI_OUT, 2, weff32, 1, DGPI_OUT, DGPE_OUT, 0);
    split_hilo3<<<dim3(DGPI_OUT / 256, DGPE_IN), 256, 0, sB>>>(weff32, weffs, DGPI_OUT);
    cudaStreamWaitEvent(sB, evW1s, 0);
    // W_full[n][i] single pass over K=4608: hi@hi | lo@hi | hi@lo   (7.2 GF)
    gemm_f16<<<dim3(DGPE_IN / BN, U3 / BM), NTHREADS, SMEM_TOTAL, sB>>>(
        w1s, w1s, 2 * DGPI_OUT, 2 * DGPI_OUT, 2 * DGPI_OUT,
        weffs, 3 * DGPI_OUT, nullptr,
        nullptr, 0, 0, wfull_h, 0, DGPE_IN, 3 * DGPI_OUT, 0);
    cudaEventRecord(evWfull, sB);

    // ---- join ----
    cudaStreamWaitEvent(0, evWfull, 0);
    cudaStreamWaitEvent(0, evBias, 0);
    cudaStreamWaitEvent(0, evW2, 0);

    // h1 = relu(x @ W_full + bias_full)   (25.8 GF)
    gemm_f16<<<dim3(U3 / BN, BATCH / BM), NTHREADS, SMEM_TOTAL>>>(
        xh, xh, DGPE_IN, DGPE_IN, DGPE_IN,
        wfull_h, DGPE_IN, bias_full,
        nullptr, 0, 0, h1, 0, U3, DGPE_IN, 1);
    // h2 = relu(h1 @ w2 + b2)   (8.6 GF)
    gemm_f16<<<dim3(U3 / BN, BATCH / BM), NTHREADS, SMEM_TOTAL>>>(
        h1, h1, U3, U3, U3,
        wt_w2, U3, b2,
        nullptr, 0, 0, h2, 0, U3, U3, 1);
    // out = relu(h2 @ w3 + b3)
    final_layer<<<BATCH / 8, 256>>>(h2, w3, b3, out);
}